// round 5
// baseline (speedup 1.0000x reference)
#include <cuda_runtime.h>
#include <cuda_bf16.h>
#include <math.h>
#include <stdint.h>

#define BATCH 4
#define NTOK  4096      // N = 64*64
#define CDIM  256
#define NH    8
#define HD    32
#define RESHW 64
#define PLP   64        // pooled length (8*8)
#define TBLN  4096
#define EPSF  1.1920929e-07f

// ---------------- scratch (device globals; no dynamic alloc) ----------------
__device__ float g_q   [BATCH*NTOK*CDIM];
__device__ float g_qs  [BATCH*NTOK*CDIM];
__device__ float g_kv  [BATCH*NTOK*2*CDIM];
__device__ float g_sr  [BATCH*NTOK*CDIM];
__device__ float g_gate[BATCH*NTOK*NH];
__device__ float g_kvp [BATCH*PLP*2*CDIM];
__device__ float g_cpb [TBLN*NH];
// bf16 hi/lo split operands for tensor-core GEMMs
__device__ __nv_bfloat16 g_xh [BATCH*NTOK*CDIM];
__device__ __nv_bfloat16 g_xl [BATCH*NTOK*CDIM];
__device__ __nv_bfloat16 g_wh [1280*CDIM];   // q(0) kv(256) sr(768) proj(1024)
__device__ __nv_bfloat16 g_wl [1280*CDIM];
__device__ __nv_bfloat16 g_ph [BATCH*PLP*CDIM];   // pooled+LN hi
__device__ __nv_bfloat16 g_pl [BATCH*PLP*CDIM];
__device__ __nv_bfloat16 g_ah [BATCH*NTOK*CDIM];  // attention out hi
__device__ __nv_bfloat16 g_al [BATCH*NTOK*CDIM];

__device__ __forceinline__ float warp_sum(float v) {
#pragma unroll
    for (int o = 16; o; o >>= 1) v += __shfl_xor_sync(0xffffffffu, v, o);
    return v;
}
__device__ __forceinline__ float warp_max(float v) {
#pragma unroll
    for (int o = 16; o; o >>= 1) v = fmaxf(v, __shfl_xor_sync(0xffffffffu, v, o));
    return v;
}

// ================= helpers ==================================================
__device__ __forceinline__ uint32_t smem_u32(const void* p) {
    uint32_t a;
    asm("{ .reg .u64 t; cvta.to.shared.u64 t, %1; cvt.u32.u64 %0, t; }"
        : "=r"(a) : "l"(p));
    return a;
}
__device__ __forceinline__ void ldsm_x4(uint32_t* r, uint32_t addr) {
    asm volatile("ldmatrix.sync.aligned.m8n8.x4.shared.b16 {%0,%1,%2,%3}, [%4];"
                 : "=r"(r[0]), "=r"(r[1]), "=r"(r[2]), "=r"(r[3]) : "r"(addr));
}
__device__ __forceinline__ void ldsm_x2(uint32_t* r, uint32_t addr) {
    asm volatile("ldmatrix.sync.aligned.m8n8.x2.shared.b16 {%0,%1}, [%2];"
                 : "=r"(r[0]), "=r"(r[1]) : "r"(addr));
}
__device__ __forceinline__ void mma_bf16(float* c, const uint32_t* a,
                                         const uint32_t* b) {
    asm volatile(
        "mma.sync.aligned.m16n8k16.row.col.f32.bf16.bf16.f32 "
        "{%0,%1,%2,%3}, {%4,%5,%6,%7}, {%8,%9}, {%0,%1,%2,%3};"
        : "+f"(c[0]), "+f"(c[1]), "+f"(c[2]), "+f"(c[3])
        : "r"(a[0]), "r"(a[1]), "r"(a[2]), "r"(a[3]), "r"(b[0]), "r"(b[1]));
}
__device__ __forceinline__ void cp16(uint32_t dst, const void* src) {
    asm volatile("cp.async.cg.shared.global [%0], [%1], 16;"
                 :: "r"(dst), "l"(src));
}
#define CP_COMMIT() asm volatile("cp.async.commit_group;" ::: "memory")
#define CP_WAIT0()  asm volatile("cp.async.wait_group 0;" ::: "memory")

// ---------------- f32 -> bf16 hi/lo split (vectorized) ----------------------
__global__ void __launch_bounds__(256)
convert_split(const float4* __restrict__ src, ushort4* __restrict__ hi,
              ushort4* __restrict__ lo, int n4) {
    int i = blockIdx.x * 256 + threadIdx.x;
    if (i >= n4) return;
    float4 v = src[i];
    __nv_bfloat16 h0 = __float2bfloat16(v.x), h1 = __float2bfloat16(v.y);
    __nv_bfloat16 h2 = __float2bfloat16(v.z), h3 = __float2bfloat16(v.w);
    __nv_bfloat16 l0 = __float2bfloat16(v.x - __bfloat162float(h0));
    __nv_bfloat16 l1 = __float2bfloat16(v.y - __bfloat162float(h1));
    __nv_bfloat16 l2 = __float2bfloat16(v.z - __bfloat162float(h2));
    __nv_bfloat16 l3 = __float2bfloat16(v.w - __bfloat162float(h3));
    ushort4 H, L;
    H.x = *(uint16_t*)&h0; H.y = *(uint16_t*)&h1;
    H.z = *(uint16_t*)&h2; H.w = *(uint16_t*)&h3;
    L.x = *(uint16_t*)&l0; L.y = *(uint16_t*)&l1;
    L.z = *(uint16_t*)&l2; L.w = *(uint16_t*)&l3;
    hi[i] = H; lo[i] = L;
}

// ================= double-buffered 3-term bf16 GEMM =========================
// C = A[*,256] @ W[*,256]^T (+bias, region epilogue). Tile 128x128, 8 warps.
// MODE 0: fused q/kv/sr outputs.  MODE 1: plain single output.
#define MATSZ (128 * 40)
#define GSMEM (2 * 4 * MATSZ * 2)   // 81920 B

template<int MODE>
__global__ void __launch_bounds__(256)
gemm_bf16(const __nv_bfloat16* __restrict__ Ah, const __nv_bfloat16* __restrict__ Al,
          const __nv_bfloat16* __restrict__ Wh, const __nv_bfloat16* __restrict__ Wl,
          float* __restrict__ C0, float* __restrict__ C1, float* __restrict__ C2,
          const float* __restrict__ b0, const float* __restrict__ b1,
          const float* __restrict__ b2, int ldc0) {
    extern __shared__ uint16_t sd[];
    const int bm = blockIdx.y * 128, bn = blockIdx.x * 128;
    const int tid = threadIdx.x, lane = tid & 31, wid = tid >> 5;
    const int wm = (wid & 3) * 32, wn = (wid >> 2) * 64;
    float acc[2][8][4] = {};

    const __nv_bfloat16* gsrc[4] = {
        Ah + (size_t)bm * 256, Al + (size_t)bm * 256,
        Wh + (size_t)bn * 256, Wl + (size_t)bn * 256};

    // prologue: load chunk 0 into stage 0
#pragma unroll
    for (int m = 0; m < 4; m++)
#pragma unroll
        for (int s = 0; s < 2; s++) {
            int seg = tid + s * 256;
            int row = seg >> 2, part = seg & 3;
            cp16(smem_u32(sd + m * MATSZ + row * 40 + part * 8),
                 gsrc[m] + (size_t)row * 256 + part * 8);
        }
    CP_COMMIT();

    for (int kc = 0; kc < 8; kc++) {
        const int stg = kc & 1;
        CP_WAIT0();
        __syncthreads();
        if (kc < 7) {
            const int nb = (stg ^ 1) * 4 * MATSZ;
            const int ko = (kc + 1) * 32;
#pragma unroll
            for (int m = 0; m < 4; m++)
#pragma unroll
                for (int s = 0; s < 2; s++) {
                    int seg = tid + s * 256;
                    int row = seg >> 2, part = seg & 3;
                    cp16(smem_u32(sd + nb + m * MATSZ + row * 40 + part * 8),
                         gsrc[m] + (size_t)row * 256 + ko + part * 8);
                }
            CP_COMMIT();
        }
        uint16_t* pAh = sd + (stg * 4 + 0) * MATSZ;
        uint16_t* pAl = sd + (stg * 4 + 1) * MATSZ;
        uint16_t* pBh = sd + (stg * 4 + 2) * MATSZ;
        uint16_t* pBl = sd + (stg * 4 + 3) * MATSZ;
#pragma unroll
        for (int ks = 0; ks < 2; ks++) {
            uint32_t ah[2][4], al[2][4];
            const int arow = lane & 15, acol = ks * 16 + (lane >> 4) * 8;
#pragma unroll
            for (int i = 0; i < 2; i++) {
                ldsm_x4(ah[i], smem_u32(pAh + (wm + i * 16 + arow) * 40 + acol));
                ldsm_x4(al[i], smem_u32(pAl + (wm + i * 16 + arow) * 40 + acol));
            }
            const int brow0 = wn + (lane & 7);
            const int bcol = ks * 16 + ((lane >> 3) & 1) * 8;
#pragma unroll
            for (int j = 0; j < 8; j++) {
                uint32_t bh[2], bl[2];
                ldsm_x2(bh, smem_u32(pBh + (brow0 + j * 8) * 40 + bcol));
                ldsm_x2(bl, smem_u32(pBl + (brow0 + j * 8) * 40 + bcol));
#pragma unroll
                for (int i = 0; i < 2; i++) {
                    mma_bf16(acc[i][j], ah[i], bh);
                    mma_bf16(acc[i][j], ah[i], bl);
                    mma_bf16(acc[i][j], al[i], bh);
                }
            }
        }
    }
    // epilogue
    float* C; const float* bias; int ldc, cb, act = 0;
    if (MODE == 0) {
        int r = bn >> 7;
        if (r < 2)      { C = C0; bias = b0; ldc = 256; cb = bn; }
        else if (r < 6) { C = C1; bias = b1; ldc = 512; cb = bn - 256; }
        else            { C = C2; bias = b2; ldc = 256; cb = bn - 768; act = 1; }
    } else {
        C = C0; bias = b0; ldc = ldc0; cb = bn;
    }
#pragma unroll
    for (int i = 0; i < 2; i++) {
        int r0 = bm + wm + i * 16 + (lane >> 2);
#pragma unroll
        for (int j = 0; j < 8; j++) {
            int col = cb + wn + j * 8 + (lane & 3) * 2;
            float bb0 = bias[col], bb1 = bias[col + 1];
            float v0 = acc[i][j][0] + bb0, v1 = acc[i][j][1] + bb1;
            float v2 = acc[i][j][2] + bb0, v3 = acc[i][j][3] + bb1;
            if (MODE == 0 && act) {
                v0 = 0.5f * v0 * (1.0f + erff(v0 * 0.70710678118654752f));
                v1 = 0.5f * v1 * (1.0f + erff(v1 * 0.70710678118654752f));
                v2 = 0.5f * v2 * (1.0f + erff(v2 * 0.70710678118654752f));
                v3 = 0.5f * v3 * (1.0f + erff(v3 * 0.70710678118654752f));
            }
            float2 o01; o01.x = v0; o01.y = v1;
            float2 o23; o23.x = v2; o23.y = v3;
            *(float2*)(C + (size_t)r0 * ldc + col) = o01;
            *(float2*)(C + (size_t)(r0 + 8) * ldc + col) = o23;
        }
    }
}

// ---------------- gating: one warp per token (float4 loads) ------------------
__global__ void __launch_bounds__(256)
gating_kernel(const float* __restrict__ x, const float* __restrict__ wg,
              const float* __restrict__ wg0, const float* __restrict__ wg1) {
    int t = blockIdx.x * 8 + (threadIdx.x >> 5);
    int lane = threadIdx.x & 31;
    const float* xt = x + (size_t)t * CDIM;
    float4 xa = *(const float4*)(xt + lane * 8);
    float4 xb = *(const float4*)(xt + lane * 8 + 4);
    float d[10];
#pragma unroll
    for (int i = 0; i < 10; i++) {
        const float* wr = (i < 4) ? wg + i * CDIM
                        : (i < 8) ? wg1 + (i - 4) * CDIM
                                  : wg0 + (i - 8) * CDIM;
        float4 wa = *(const float4*)(wr + lane * 8);
        float4 wb = *(const float4*)(wr + lane * 8 + 4);
        float s = xa.x * wa.x + xa.y * wa.y + xa.z * wa.z + xa.w * wa.w
                + xb.x * wb.x + xb.y * wb.y + xb.z * wb.z + xb.w * wb.w;
        d[i] = warp_sum(s);
    }
    float m0 = fmaxf(fmaxf(d[0], d[1]), fmaxf(d[2], d[3]));
    float e[4], se = 0.f;
#pragma unroll
    for (int i = 0; i < 4; i++) { e[i] = expf(d[i] - m0); se += e[i]; }
    float gsm[4];
#pragma unroll
    for (int i = 0; i < 4; i++) gsm[i] = e[i] / se;
    int i1 = 0;
#pragma unroll
    for (int i = 1; i < 4; i++) if (gsm[i] > gsm[i1]) i1 = i;
    int i2 = -1;
#pragma unroll
    for (int i = 0; i < 4; i++) {
        if (i == i1) continue;
        if (i2 < 0 || gsm[i] > gsm[i2]) i2 = i;
    }
    float rs = fmaxf(gsm[i1] + gsm[i2], EPSF);
    float routed[4];
#pragma unroll
    for (int i = 0; i < 4; i++)
        routed[i] = (i == i1 || i == i2) ? gsm[i] / rs * 2.f : 0.f;
    float m1 = fmaxf(fmaxf(d[4], d[5]), fmaxf(d[6], d[7]));
    float es[4], ss = 0.f;
#pragma unroll
    for (int i = 0; i < 4; i++) { es[i] = expf(d[4 + i] - m1); ss += es[i]; }
    float shg[4];
#pragma unroll
    for (int i = 0; i < 4; i++) shg[i] = es[i] / ss * 4.f;
    float m2 = fmaxf(d[8], d[9]);
    float e8 = expf(d[8] - m2), e9 = expf(d[9] - m2);
    float w00 = e8 / (e8 + e9) * 2.f;
    float w01 = e9 / (e8 + e9) * 2.f;
    if (lane < NH) {
        float v = (lane < 4) ? w00 * shg[lane] : w01 * routed[lane - 4];
        g_gate[(size_t)t * NH + lane] = v;
    }
}

// ---------------- q postprocess ---------------------------------------------
__global__ void __launch_bounds__(256)
q_post(const float* __restrict__ temp, const float* __restrict__ qe) {
    int bn = blockIdx.x;
    int h = threadIdx.x >> 5, lane = threadIdx.x & 31;
    int n = bn & (NTOK - 1);
    size_t off = (size_t)bn * CDIM + h * HD + lane;
    float v = g_q[off];
    float nrm = sqrtf(warp_sum(v * v));
    float qn = v / fmaxf(nrm, EPSF);
    int y = n >> 6, x = n & 63;
    int ch = min(y + 1, 63) - max(y - 1, 0) + 1;
    int cw = min(x + 1, 63) - max(x - 1, 0) + 1;
    float sls = logf((float)(ch * cw + PLP));
    float sp = log1pf(expf(temp[h]));
    g_q [off] = qn;
    g_qs[off] = (qn + qe[h * HD + lane]) * sp * sls;
}

__global__ void __launch_bounds__(256) kv_post() {
    int bn = blockIdx.x;
    int h = threadIdx.x >> 5, lane = threadIdx.x & 31;
    size_t off = (size_t)bn * 2 * CDIM + h * HD + lane;
    float v = g_kv[off];
    float nrm = sqrtf(warp_sum(v * v));
    g_kv[off] = v / fmaxf(nrm, EPSF);
}

__global__ void __launch_bounds__(256) kvpool_post() {
    int bp = blockIdx.x;
    int h = threadIdx.x >> 5, lane = threadIdx.x & 31;
    size_t off = (size_t)bp * 2 * CDIM + h * HD + lane;
    float v = g_kvp[off];
    float nrm = sqrtf(warp_sum(v * v));
    g_kvp[off] = v / fmaxf(nrm, EPSF);
}

// ---------------- 8x8 avg pool + LayerNorm (writes bf16 hi/lo) --------------
__global__ void __launch_bounds__(256)
pool_ln(const float* __restrict__ gw, const float* __restrict__ gb) {
    int bp = blockIdx.x;
    int b = bp >> 6, p = bp & 63;
    int py = p >> 3, px = p & 7;
    int c = threadIdx.x;
    const float* base = g_sr + (size_t)b * NTOK * CDIM;
    float s = 0.f;
    for (int iy = 0; iy < 8; iy++) {
        int y = py * 8 + iy;
        for (int ix = 0; ix < 8; ix++) {
            int n = y * RESHW + px * 8 + ix;
            s += base[(size_t)n * CDIM + c];
        }
    }
    float val = s * (1.0f / 64.0f);
    __shared__ float red[256];
    red[c] = val; __syncthreads();
    for (int st = 128; st > 0; st >>= 1) { if (c < st) red[c] += red[c + st]; __syncthreads(); }
    float mu = red[0] * (1.0f / 256.0f);
    __syncthreads();
    float dv = val - mu;
    red[c] = dv * dv; __syncthreads();
    for (int st = 128; st > 0; st >>= 1) { if (c < st) red[c] += red[c + st]; __syncthreads(); }
    float var = red[0] * (1.0f / 256.0f);
    float ov = dv * rsqrtf(var + 1e-5f) * gw[c] + gb[c];
    __nv_bfloat16 h = __float2bfloat16(ov);
    g_ph[(size_t)bp * CDIM + c] = h;
    g_pl[(size_t)bp * CDIM + c] = __float2bfloat16(ov - __bfloat162float(h));
}

// ---------------- cpb MLP ----------------------------------------------------
__global__ void __launch_bounds__(128)
cpb_kernel(const float* __restrict__ tbl, const float* __restrict__ w1,
           const float* __restrict__ b1, const float* __restrict__ w2,
           const float* __restrict__ b2) {
    int row = blockIdx.x;
    int tid = threadIdx.x;
    float t0 = tbl[row * 2 + 0], t1 = tbl[row * 2 + 1];
    float acc[8] = {};
    for (int j = tid; j < 512; j += 128) {
        float hv = fmaxf(t0 * w1[2 * j] + t1 * w1[2 * j + 1] + b1[j], 0.f);
#pragma unroll
        for (int o = 0; o < 8; o++) acc[o] += hv * w2[o * 512 + j];
    }
#pragma unroll
    for (int o = 0; o < 8; o++) acc[o] = warp_sum(acc[o]);
    __shared__ float sh[4][8];
    int wp = tid >> 5, lane = tid & 31;
    if (lane == 0)
#pragma unroll
        for (int o = 0; o < 8; o++) sh[wp][o] = acc[o];
    __syncthreads();
    if (tid < 8)
        g_cpb[(size_t)row * 8 + tid] =
            sh[0][tid] + sh[1][tid] + sh[2][tid] + sh[3][tid] + b2[tid];
}

// ---------------- fused attention: 32 tokens per block -----------------------
__global__ void __launch_bounds__(1024)
attn_kernel(const float* __restrict__ rpb, const float* __restrict__ lt,
            const float* __restrict__ lb, const int* __restrict__ rel_idx) {
    int blk = blockIdx.x;
    int ntile = blk & 127;
    int hh = (blk >> 7) & 7;
    int b = blk >> 10;
    int w = threadIdx.x >> 5, lane = threadIdx.x & 31;
    __shared__ float kp[64][33];
    __shared__ float vp[64][33];
    __shared__ float logit[32][80];
    __shared__ float qsh[32][32];
    for (int i = threadIdx.x; i < 64 * 32; i += 1024) {
        int p = i >> 5, d = i & 31;
        size_t base = (size_t)(b * PLP + p) * 2 * CDIM + hh * HD + d;
        kp[p][d] = g_kvp[base];
        vp[p][d] = g_kvp[base + CDIM];
    }
    __syncthreads();
    int n = ntile * 32 + w;
    int y = n >> 6, x = n & 63;
    size_t qoff = (size_t)(b * NTOK + n) * CDIM + hh * HD + lane;
    float qsv = g_qs[qoff];
    float qnv = g_q[qoff];
    qsh[w][lane] = qsv;
#pragma unroll
    for (int l = 0; l < 9; l++) {
        int yy = y + l / 3 - 1, xx = x + l % 3 - 1;
        float dot = 0.f;
        if ((unsigned)yy < 64u && (unsigned)xx < 64u) {
            int n2 = yy * RESHW + xx;
            dot = warp_sum(qsv * g_kv[(size_t)(b * NTOK + n2) * 2 * CDIM + hh * HD + lane]);
        }
        if (lane == 0) logit[w][l] = dot + rpb[hh * 9 + l];
    }
    __syncwarp();
    const int* ridx = rel_idx + (size_t)n * PLP;
#pragma unroll
    for (int rr = 0; rr < 2; rr++) {
        int p = lane + rr * 32;
        float dot = 0.f;
#pragma unroll
        for (int j = 0; j < 32; j++) dot += qsh[w][j] * kp[p][j];
        logit[w][9 + p] = dot + g_cpb[(size_t)ridx[p] * 8 + hh];
    }
    __syncwarp();
    float v0 = logit[w][lane];
    float v1 = logit[w][lane + 32];
    float v2 = (lane < 9) ? logit[w][lane + 64] : -3.4e38f;
    float mx = warp_max(fmaxf(fmaxf(v0, v1), v2));
    float e0 = expf(v0 - mx), e1 = expf(v1 - mx);
    float e2 = (lane < 9) ? expf(v2 - mx) : 0.f;
    float inv = 1.0f / warp_sum(e0 + e1 + e2);
    logit[w][lane] = e0 * inv;
    logit[w][lane + 32] = e1 * inv;
    if (lane < 9) logit[w][lane + 64] = e2 * inv;
    __syncwarp();
#pragma unroll
    for (int l = 0; l < 9; l++) {
        float d2 = warp_sum(qnv * lt[hh * (HD * 9) + lane * 9 + l]);
        if (lane == 0) logit[w][l] += d2 + lb[hh * 9 + l];
    }
    __syncwarp();
    float outv = 0.f;
#pragma unroll
    for (int l = 0; l < 9; l++) {
        int yy = y + l / 3 - 1, xx = x + l % 3 - 1;
        if ((unsigned)yy < 64u && (unsigned)xx < 64u) {
            int n2 = yy * RESHW + xx;
            outv += logit[w][l] *
                    g_kv[(size_t)(b * NTOK + n2) * 2 * CDIM + CDIM + hh * HD + lane];
        }
    }
#pragma unroll 8
    for (int p = 0; p < 64; p++) outv += logit[w][9 + p] * vp[p][lane];
    float gt = g_gate[(size_t)(b * NTOK + n) * NH + hh];
    float val = outv * gt;
    __nv_bfloat16 vh = __float2bfloat16(val);
    size_t oidx = (size_t)(b * NTOK + n) * CDIM + hh * HD + lane;
    g_ah[oidx] = vh;
    g_al[oidx] = __float2bfloat16(val - __bfloat162float(vh));
}

// ---------------- launch ----------------------------------------------------
extern "C" void kernel_launch(void* const* d_in, const int* in_sizes, int n_in,
                              void* d_out, int out_size) {
    const float* x      = (const float*)d_in[0];
    const float* rct    = (const float*)d_in[1];
    const float* q_w    = (const float*)d_in[2];
    const float* q_b    = (const float*)d_in[3];
    const float* kv_w   = (const float*)d_in[4];
    const float* kv_b   = (const float*)d_in[5];
    const float* temp   = (const float*)d_in[6];
    const float* qe     = (const float*)d_in[7];
    const float* rpb    = (const float*)d_in[8];
    const float* lt     = (const float*)d_in[9];
    const float* lb     = (const float*)d_in[10];
    const float* cpb1_w = (const float*)d_in[11];
    const float* cpb1_b = (const float*)d_in[12];
    const float* cpb2_w = (const float*)d_in[13];
    const float* cpb2_b = (const float*)d_in[14];
    const float* sr_w   = (const float*)d_in[15];
    const float* sr_b   = (const float*)d_in[16];
    const float* norm_g = (const float*)d_in[17];
    const float* norm_b = (const float*)d_in[18];
    const float* wg_w   = (const float*)d_in[19];
    const float* wg0_w  = (const float*)d_in[20];
    const float* wg1_w  = (const float*)d_in[21];
    const float* proj_w = (const float*)d_in[22];
    const float* proj_b = (const float*)d_in[23];
    const int*   ridx   = (const int*)d_in[24];
    float* out = (float*)d_out;

    float *pq, *pkv, *psr, *pkvp;
    __nv_bfloat16 *pxh, *pxl, *pwh, *pwl, *pph, *ppl, *pah, *pal;
    cudaGetSymbolAddress((void**)&pq,  g_q);
    cudaGetSymbolAddress((void**)&pkv, g_kv);
    cudaGetSymbolAddress((void**)&psr, g_sr);
    cudaGetSymbolAddress((void**)&pkvp, g_kvp);
    cudaGetSymbolAddress((void**)&pxh, g_xh);
    cudaGetSymbolAddress((void**)&pxl, g_xl);
    cudaGetSymbolAddress((void**)&pwh, g_wh);
    cudaGetSymbolAddress((void**)&pwl, g_wl);
    cudaGetSymbolAddress((void**)&pph, g_ph);
    cudaGetSymbolAddress((void**)&ppl, g_pl);
    cudaGetSymbolAddress((void**)&pah, g_ah);
    cudaGetSymbolAddress((void**)&pal, g_al);

    cudaFuncSetAttribute(gemm_bf16<0>,
                         cudaFuncAttributeMaxDynamicSharedMemorySize, GSMEM);
    cudaFuncSetAttribute(gemm_bf16<1>,
                         cudaFuncAttributeMaxDynamicSharedMemorySize, GSMEM);

    const int M = BATCH * NTOK;                       // 16384

    // split passes
    convert_split<<<M * CDIM / 4 / 256, 256>>>(
        (const float4*)x, (ushort4*)pxh, (ushort4*)pxl, M * CDIM / 4);
    convert_split<<<64, 256>>>((const float4*)q_w,
        (ushort4*)pwh, (ushort4*)pwl, 256 * 256 / 4);
    convert_split<<<128, 256>>>((const float4*)kv_w,
        (ushort4*)(pwh + 256 * 256), (ushort4*)(pwl + 256 * 256), 512 * 256 / 4);
    convert_split<<<64, 256>>>((const float4*)sr_w,
        (ushort4*)(pwh + 768 * 256), (ushort4*)(pwl + 768 * 256), 256 * 256 / 4);
    convert_split<<<64, 256>>>((const float4*)proj_w,
        (ushort4*)(pwh + 1024 * 256), (ushort4*)(pwl + 1024 * 256), 256 * 256 / 4);

    // fused q/kv/sr GEMM
    dim3 gf(8, M / 128);
    gemm_bf16<0><<<gf, 256, GSMEM>>>(pxh, pxl, pwh, pwl,
                                     pq, pkv, psr, q_b, kv_b, sr_b, 0);
    gating_kernel<<<M / 8, 256>>>(x, wg_w, wg0_w, wg1_w);
    q_post<<<M, 256>>>(temp, qe);
    kv_post<<<M, 256>>>();
    pool_ln<<<BATCH * PLP, 256>>>(norm_g, norm_b);
    dim3 gp(4, 2);
    gemm_bf16<1><<<gp, 256, GSMEM>>>(pph, ppl, pwh + 256 * 256, pwl + 256 * 256,
                                     pkvp, nullptr, nullptr, kv_b, nullptr,
                                     nullptr, 512);
    kvpool_post<<<BATCH * PLP, 256>>>();
    cpb_kernel<<<TBLN, 128>>>(rct, cpb1_w, cpb1_b, cpb2_w, cpb2_b);
    attn_kernel<<<BATCH * NH * (NTOK / 32), 1024>>>(rpb, lt, lb, ridx);
    dim3 gj(2, M / 128);
    gemm_bf16<1><<<gj, 256, GSMEM>>>(pah, pal, pwh + 1024 * 256, pwl + 1024 * 256,
                                     out, nullptr, nullptr, proj_b, nullptr,
                                     nullptr, 256);
}

// round 6
// speedup vs baseline: 1.0059x; 1.0059x over previous
#include <cuda_runtime.h>
#include <cuda_bf16.h>
#include <math.h>
#include <stdint.h>

#define BATCH 4
#define NTOK  4096      // N = 64*64
#define CDIM  256
#define NH    8
#define HD    32
#define RESHW 64
#define PLP   64        // pooled length (8*8)
#define TBLN  4096
#define EPSF  1.1920929e-07f

// ---------------- scratch (device globals; no dynamic alloc) ----------------
__device__ float g_q   [BATCH*NTOK*CDIM];
__device__ float g_qs  [BATCH*NTOK*CDIM];
__device__ float g_kv  [BATCH*NTOK*2*CDIM];
__device__ float g_sr  [BATCH*NTOK*CDIM];
__device__ float g_gate[BATCH*NTOK*NH];
__device__ float g_kvp [BATCH*PLP*2*CDIM];
__device__ float g_cpb [TBLN*NH];
__device__ __nv_bfloat16 g_xh [BATCH*NTOK*CDIM];
__device__ __nv_bfloat16 g_xl [BATCH*NTOK*CDIM];
__device__ __nv_bfloat16 g_wh [1280*CDIM];   // q(0) kv(256) sr(768) proj(1024)
__device__ __nv_bfloat16 g_wl [1280*CDIM];
__device__ __nv_bfloat16 g_ph [BATCH*PLP*CDIM];
__device__ __nv_bfloat16 g_pl [BATCH*PLP*CDIM];
__device__ __nv_bfloat16 g_ah [BATCH*NTOK*CDIM];
__device__ __nv_bfloat16 g_al [BATCH*NTOK*CDIM];

__device__ __forceinline__ float warp_sum(float v) {
#pragma unroll
    for (int o = 16; o; o >>= 1) v += __shfl_xor_sync(0xffffffffu, v, o);
    return v;
}
__device__ __forceinline__ float warp_max(float v) {
#pragma unroll
    for (int o = 16; o; o >>= 1) v = fmaxf(v, __shfl_xor_sync(0xffffffffu, v, o));
    return v;
}

// ================= helpers ==================================================
__device__ __forceinline__ uint32_t smem_u32(const void* p) {
    uint32_t a;
    asm("{ .reg .u64 t; cvta.to.shared.u64 t, %1; cvt.u32.u64 %0, t; }"
        : "=r"(a) : "l"(p));
    return a;
}
__device__ __forceinline__ void ldsm_x4(uint32_t* r, uint32_t addr) {
    asm volatile("ldmatrix.sync.aligned.m8n8.x4.shared.b16 {%0,%1,%2,%3}, [%4];"
                 : "=r"(r[0]), "=r"(r[1]), "=r"(r[2]), "=r"(r[3]) : "r"(addr));
}
__device__ __forceinline__ void ldsm_x2(uint32_t* r, uint32_t addr) {
    asm volatile("ldmatrix.sync.aligned.m8n8.x2.shared.b16 {%0,%1}, [%2];"
                 : "=r"(r[0]), "=r"(r[1]) : "r"(addr));
}
__device__ __forceinline__ void mma_bf16(float* c, const uint32_t* a,
                                         const uint32_t* b) {
    asm volatile(
        "mma.sync.aligned.m16n8k16.row.col.f32.bf16.bf16.f32 "
        "{%0,%1,%2,%3}, {%4,%5,%6,%7}, {%8,%9}, {%0,%1,%2,%3};"
        : "+f"(c[0]), "+f"(c[1]), "+f"(c[2]), "+f"(c[3])
        : "r"(a[0]), "r"(a[1]), "r"(a[2]), "r"(a[3]), "r"(b[0]), "r"(b[1]));
}
__device__ __forceinline__ void cp16(uint32_t dst, const void* src) {
    asm volatile("cp.async.cg.shared.global [%0], [%1], 16;"
                 :: "r"(dst), "l"(src));
}
#define CP_COMMIT() asm volatile("cp.async.commit_group;" ::: "memory")
#define CP_WAIT0()  asm volatile("cp.async.wait_group 0;" ::: "memory")

__device__ __forceinline__ void split4(float4 v, ushort4& H, ushort4& L) {
    __nv_bfloat16 h0 = __float2bfloat16(v.x), h1 = __float2bfloat16(v.y);
    __nv_bfloat16 h2 = __float2bfloat16(v.z), h3 = __float2bfloat16(v.w);
    __nv_bfloat16 l0 = __float2bfloat16(v.x - __bfloat162float(h0));
    __nv_bfloat16 l1 = __float2bfloat16(v.y - __bfloat162float(h1));
    __nv_bfloat16 l2 = __float2bfloat16(v.z - __bfloat162float(h2));
    __nv_bfloat16 l3 = __float2bfloat16(v.w - __bfloat162float(h3));
    H.x = *(uint16_t*)&h0; H.y = *(uint16_t*)&h1;
    H.z = *(uint16_t*)&h2; H.w = *(uint16_t*)&h3;
    L.x = *(uint16_t*)&l0; L.y = *(uint16_t*)&l1;
    L.z = *(uint16_t*)&l2; L.w = *(uint16_t*)&l3;
}

// ---------------- x convert + gating (single x read) ------------------------
__global__ void __launch_bounds__(256)
conv_x_gate(const float* __restrict__ x, const float* __restrict__ wg,
            const float* __restrict__ wg0, const float* __restrict__ wg1) {
    int t = blockIdx.x * 8 + (threadIdx.x >> 5);
    int lane = threadIdx.x & 31;
    const float* xt = x + (size_t)t * CDIM;
    float4 xa = *(const float4*)(xt + lane * 8);
    float4 xb = *(const float4*)(xt + lane * 8 + 4);
    // convert + store hi/lo
    ushort4 Ha, La, Hb, Lb;
    split4(xa, Ha, La);
    split4(xb, Hb, Lb);
    ushort4* ph = (ushort4*)(g_xh + (size_t)t * CDIM + lane * 8);
    ushort4* pl = (ushort4*)(g_xl + (size_t)t * CDIM + lane * 8);
    ph[0] = Ha; ph[1] = Hb;
    pl[0] = La; pl[1] = Lb;
    // gating
    float d[10];
#pragma unroll
    for (int i = 0; i < 10; i++) {
        const float* wr = (i < 4) ? wg + i * CDIM
                        : (i < 8) ? wg1 + (i - 4) * CDIM
                                  : wg0 + (i - 8) * CDIM;
        float4 wa = *(const float4*)(wr + lane * 8);
        float4 wb = *(const float4*)(wr + lane * 8 + 4);
        float s = xa.x * wa.x + xa.y * wa.y + xa.z * wa.z + xa.w * wa.w
                + xb.x * wb.x + xb.y * wb.y + xb.z * wb.z + xb.w * wb.w;
        d[i] = warp_sum(s);
    }
    float m0 = fmaxf(fmaxf(d[0], d[1]), fmaxf(d[2], d[3]));
    float e[4], se = 0.f;
#pragma unroll
    for (int i = 0; i < 4; i++) { e[i] = expf(d[i] - m0); se += e[i]; }
    float gsm[4];
#pragma unroll
    for (int i = 0; i < 4; i++) gsm[i] = e[i] / se;
    int i1 = 0;
#pragma unroll
    for (int i = 1; i < 4; i++) if (gsm[i] > gsm[i1]) i1 = i;
    int i2 = -1;
#pragma unroll
    for (int i = 0; i < 4; i++) {
        if (i == i1) continue;
        if (i2 < 0 || gsm[i] > gsm[i2]) i2 = i;
    }
    float rs = fmaxf(gsm[i1] + gsm[i2], EPSF);
    float routed[4];
#pragma unroll
    for (int i = 0; i < 4; i++)
        routed[i] = (i == i1 || i == i2) ? gsm[i] / rs * 2.f : 0.f;
    float m1 = fmaxf(fmaxf(d[4], d[5]), fmaxf(d[6], d[7]));
    float es[4], ss = 0.f;
#pragma unroll
    for (int i = 0; i < 4; i++) { es[i] = expf(d[4 + i] - m1); ss += es[i]; }
    float shg[4];
#pragma unroll
    for (int i = 0; i < 4; i++) shg[i] = es[i] / ss * 4.f;
    float m2 = fmaxf(d[8], d[9]);
    float e8 = expf(d[8] - m2), e9 = expf(d[9] - m2);
    float w00 = e8 / (e8 + e9) * 2.f;
    float w01 = e9 / (e8 + e9) * 2.f;
    if (lane < NH) {
        float v = (lane < 4) ? w00 * shg[lane] : w01 * routed[lane - 4];
        g_gate[(size_t)t * NH + lane] = v;
    }
}

// ---------------- all-weights convert (one launch) ---------------------------
__global__ void __launch_bounds__(256)
conv_w(const float* __restrict__ qw, const float* __restrict__ kvw,
       const float* __restrict__ srw, const float* __restrict__ pjw) {
    int i = blockIdx.x * 256 + threadIdx.x;   // float4 index, 81920 total
    int row = i >> 6;
    const float4* src;
    int off;
    if (row < 256)       { src = (const float4*)qw;  off = i; }
    else if (row < 768)  { src = (const float4*)kvw; off = i - 256 * 64; }
    else if (row < 1024) { src = (const float4*)srw; off = i - 768 * 64; }
    else                 { src = (const float4*)pjw; off = i - 1024 * 64; }
    ushort4 H, L;
    split4(src[off], H, L);
    ((ushort4*)g_wh)[i] = H;
    ((ushort4*)g_wl)[i] = L;
}

// ================= double-buffered 3-term bf16 GEMM =========================
#define MATSZ (128 * 40)
#define GSMEM (2 * 4 * MATSZ * 2)   // 81920 B

template<int MODE>
__global__ void __launch_bounds__(256)
gemm_bf16(const __nv_bfloat16* __restrict__ Ah, const __nv_bfloat16* __restrict__ Al,
          const __nv_bfloat16* __restrict__ Wh, const __nv_bfloat16* __restrict__ Wl,
          float* __restrict__ C0, float* __restrict__ C1, float* __restrict__ C2,
          const float* __restrict__ b0, const float* __restrict__ b1,
          const float* __restrict__ b2, int ldc0) {
    extern __shared__ uint16_t sd[];
    const int bm = blockIdx.y * 128, bn = blockIdx.x * 128;
    const int tid = threadIdx.x, lane = tid & 31, wid = tid >> 5;
    const int wm = (wid & 3) * 32, wn = (wid >> 2) * 64;
    float acc[2][8][4] = {};

    const __nv_bfloat16* gsrc[4] = {
        Ah + (size_t)bm * 256, Al + (size_t)bm * 256,
        Wh + (size_t)bn * 256, Wl + (size_t)bn * 256};

#pragma unroll
    for (int m = 0; m < 4; m++)
#pragma unroll
        for (int s = 0; s < 2; s++) {
            int seg = tid + s * 256;
            int row = seg >> 2, part = seg & 3;
            cp16(smem_u32(sd + m * MATSZ + row * 40 + part * 8),
                 gsrc[m] + (size_t)row * 256 + part * 8);
        }
    CP_COMMIT();

    for (int kc = 0; kc < 8; kc++) {
        const int stg = kc & 1;
        CP_WAIT0();
        __syncthreads();
        if (kc < 7) {
            const int nb = (stg ^ 1) * 4 * MATSZ;
            const int ko = (kc + 1) * 32;
#pragma unroll
            for (int m = 0; m < 4; m++)
#pragma unroll
                for (int s = 0; s < 2; s++) {
                    int seg = tid + s * 256;
                    int row = seg >> 2, part = seg & 3;
                    cp16(smem_u32(sd + nb + m * MATSZ + row * 40 + part * 8),
                         gsrc[m] + (size_t)row * 256 + ko + part * 8);
                }
            CP_COMMIT();
        }
        uint16_t* pAh = sd + (stg * 4 + 0) * MATSZ;
        uint16_t* pAl = sd + (stg * 4 + 1) * MATSZ;
        uint16_t* pBh = sd + (stg * 4 + 2) * MATSZ;
        uint16_t* pBl = sd + (stg * 4 + 3) * MATSZ;
#pragma unroll
        for (int ks = 0; ks < 2; ks++) {
            uint32_t ah[2][4], al[2][4];
            const int arow = lane & 15, acol = ks * 16 + (lane >> 4) * 8;
#pragma unroll
            for (int i = 0; i < 2; i++) {
                ldsm_x4(ah[i], smem_u32(pAh + (wm + i * 16 + arow) * 40 + acol));
                ldsm_x4(al[i], smem_u32(pAl + (wm + i * 16 + arow) * 40 + acol));
            }
            const int brow0 = wn + (lane & 7);
            const int bcol = ks * 16 + ((lane >> 3) & 1) * 8;
#pragma unroll
            for (int j = 0; j < 8; j++) {
                uint32_t bh[2], bl[2];
                ldsm_x2(bh, smem_u32(pBh + (brow0 + j * 8) * 40 + bcol));
                ldsm_x2(bl, smem_u32(pBl + (brow0 + j * 8) * 40 + bcol));
#pragma unroll
                for (int i = 0; i < 2; i++) {
                    mma_bf16(acc[i][j], ah[i], bh);
                    mma_bf16(acc[i][j], ah[i], bl);
                    mma_bf16(acc[i][j], al[i], bh);
                }
            }
        }
    }
    float* C; const float* bias; int ldc, cb, act = 0;
    if (MODE == 0) {
        int r = bn >> 7;
        if (r < 2)      { C = C0; bias = b0; ldc = 256; cb = bn; }
        else if (r < 6) { C = C1; bias = b1; ldc = 512; cb = bn - 256; }
        else            { C = C2; bias = b2; ldc = 256; cb = bn - 768; act = 1; }
    } else {
        C = C0; bias = b0; ldc = ldc0; cb = bn;
    }
#pragma unroll
    for (int i = 0; i < 2; i++) {
        int r0 = bm + wm + i * 16 + (lane >> 2);
#pragma unroll
        for (int j = 0; j < 8; j++) {
            int col = cb + wn + j * 8 + (lane & 3) * 2;
            float bb0 = bias[col], bb1 = bias[col + 1];
            float v0 = acc[i][j][0] + bb0, v1 = acc[i][j][1] + bb1;
            float v2 = acc[i][j][2] + bb0, v3 = acc[i][j][3] + bb1;
            if (MODE == 0 && act) {
                v0 = 0.5f * v0 * (1.0f + erff(v0 * 0.70710678118654752f));
                v1 = 0.5f * v1 * (1.0f + erff(v1 * 0.70710678118654752f));
                v2 = 0.5f * v2 * (1.0f + erff(v2 * 0.70710678118654752f));
                v3 = 0.5f * v3 * (1.0f + erff(v3 * 0.70710678118654752f));
            }
            float2 o01; o01.x = v0; o01.y = v1;
            float2 o23; o23.x = v2; o23.y = v3;
            *(float2*)(C + (size_t)r0 * ldc + col) = o01;
            *(float2*)(C + (size_t)(r0 + 8) * ldc + col) = o23;
        }
    }
}

// ---------------- q postprocess ---------------------------------------------
__global__ void __launch_bounds__(256)
q_post(const float* __restrict__ temp, const float* __restrict__ qe) {
    int bn = blockIdx.x;
    int h = threadIdx.x >> 5, lane = threadIdx.x & 31;
    int n = bn & (NTOK - 1);
    size_t off = (size_t)bn * CDIM + h * HD + lane;
    float v = g_q[off];
    float nrm = sqrtf(warp_sum(v * v));
    float qn = v / fmaxf(nrm, EPSF);
    int y = n >> 6, x = n & 63;
    int ch = min(y + 1, 63) - max(y - 1, 0) + 1;
    int cw = min(x + 1, 63) - max(x - 1, 0) + 1;
    float sls = logf((float)(ch * cw + PLP));
    float sp = log1pf(expf(temp[h]));
    g_q [off] = qn;
    g_qs[off] = (qn + qe[h * HD + lane]) * sp * sls;
}

__global__ void __launch_bounds__(256) kv_post() {
    int bn = blockIdx.x;
    int h = threadIdx.x >> 5, lane = threadIdx.x & 31;
    size_t off = (size_t)bn * 2 * CDIM + h * HD + lane;
    float v = g_kv[off];
    float nrm = sqrtf(warp_sum(v * v));
    g_kv[off] = v / fmaxf(nrm, EPSF);
}

__global__ void __launch_bounds__(256) kvpool_post() {
    int bp = blockIdx.x;
    int h = threadIdx.x >> 5, lane = threadIdx.x & 31;
    size_t off = (size_t)bp * 2 * CDIM + h * HD + lane;
    float v = g_kvp[off];
    float nrm = sqrtf(warp_sum(v * v));
    g_kvp[off] = v / fmaxf(nrm, EPSF);
}

// ---------------- 8x8 avg pool + LayerNorm (writes bf16 hi/lo) --------------
__global__ void __launch_bounds__(256)
pool_ln(const float* __restrict__ gw, const float* __restrict__ gb) {
    int bp = blockIdx.x;
    int b = bp >> 6, p = bp & 63;
    int py = p >> 3, px = p & 7;
    int c = threadIdx.x;
    const float* base = g_sr + (size_t)b * NTOK * CDIM;
    float s = 0.f;
    for (int iy = 0; iy < 8; iy++) {
        int y = py * 8 + iy;
        for (int ix = 0; ix < 8; ix++) {
            int n = y * RESHW + px * 8 + ix;
            s += base[(size_t)n * CDIM + c];
        }
    }
    float val = s * (1.0f / 64.0f);
    __shared__ float red[256];
    red[c] = val; __syncthreads();
    for (int st = 128; st > 0; st >>= 1) { if (c < st) red[c] += red[c + st]; __syncthreads(); }
    float mu = red[0] * (1.0f / 256.0f);
    __syncthreads();
    float dv = val - mu;
    red[c] = dv * dv; __syncthreads();
    for (int st = 128; st > 0; st >>= 1) { if (c < st) red[c] += red[c + st]; __syncthreads(); }
    float var = red[0] * (1.0f / 256.0f);
    float ov = dv * rsqrtf(var + 1e-5f) * gw[c] + gb[c];
    __nv_bfloat16 h = __float2bfloat16(ov);
    g_ph[(size_t)bp * CDIM + c] = h;
    g_pl[(size_t)bp * CDIM + c] = __float2bfloat16(ov - __bfloat162float(h));
}

// ---------------- cpb MLP ----------------------------------------------------
__global__ void __launch_bounds__(128)
cpb_kernel(const float* __restrict__ tbl, const float* __restrict__ w1,
           const float* __restrict__ b1, const float* __restrict__ w2,
           const float* __restrict__ b2) {
    int row = blockIdx.x;
    int tid = threadIdx.x;
    float t0 = tbl[row * 2 + 0], t1 = tbl[row * 2 + 1];
    float acc[8] = {};
    for (int j = tid; j < 512; j += 128) {
        float hv = fmaxf(t0 * w1[2 * j] + t1 * w1[2 * j + 1] + b1[j], 0.f);
#pragma unroll
        for (int o = 0; o < 8; o++) acc[o] += hv * w2[o * 512 + j];
    }
#pragma unroll
    for (int o = 0; o < 8; o++) acc[o] = warp_sum(acc[o]);
    __shared__ float sh[4][8];
    int wp = tid >> 5, lane = tid & 31;
    if (lane == 0)
#pragma unroll
        for (int o = 0; o < 8; o++) sh[wp][o] = acc[o];
    __syncthreads();
    if (tid < 8)
        g_cpb[(size_t)row * 8 + tid] =
            sh[0][tid] + sh[1][tid] + sh[2][tid] + sh[3][tid] + b2[tid];
}

// ---------------- fused attention: lane-serial outputs, smem staging ---------
// block = (b, hh, 32-token row tile); warp = token; no warp reductions except softmax.
#define AOKW 0
#define AOVW 3366
#define AOKP 6732
#define AOVP 8844
#define AOQS 10956
#define AOQN 12012
#define AOLG 13068
#define AOLT 15756
#define ASMEMB ((15756 + 9 * 33 + 3) * 4)   // bytes

__global__ void __launch_bounds__(1024)
attn_kernel(const float* __restrict__ rpb, const float* __restrict__ lt,
            const float* __restrict__ lb, const int* __restrict__ rel_idx) {
    extern __shared__ float sh[];
    float* Kw  = sh + AOKW;    // [102][33]  3 rows x 34 cols window
    float* Vw  = sh + AOVW;
    float* kp  = sh + AOKP;    // [64][33]
    float* vp  = sh + AOVP;
    float* qss = sh + AOQS;    // [32][33]
    float* qns = sh + AOQN;
    float* lg  = sh + AOLG;    // [32][84]
    float* lts = sh + AOLT;    // [9][33]
    int blk = blockIdx.x;
    int ntile = blk & 127;
    int hh = (blk >> 7) & 7;
    int b = blk >> 10;
    int tid = threadIdx.x, w = tid >> 5, lane = tid & 31;
    int y = ntile >> 1, x0 = (ntile & 1) << 5;

    // stage pooled K/V
    for (int i = tid; i < 2048; i += 1024) {
        int p = i >> 5, d = i & 31;
        size_t base = ((size_t)(b * PLP + p)) * 512 + hh * 32 + d;
        kp[p * 33 + d] = g_kvp[base];
        vp[p * 33 + d] = g_kvp[base + 256];
    }
    // stage local window (zero-padded OOB)
    for (int i = tid; i < 3264; i += 1024) {
        int vec = i >> 5, d = i & 31;
        int r = vec / 34, c = vec - r * 34;
        int yy = y + r - 1, xx = x0 - 1 + c;
        float kv0 = 0.f, vv0 = 0.f;
        if ((unsigned)yy < 64u && (unsigned)xx < 64u) {
            size_t base = ((size_t)(b * NTOK + yy * 64 + xx)) * 512 + hh * 32 + d;
            kv0 = g_kv[base];
            vv0 = g_kv[base + 256];
        }
        Kw[vec * 33 + d] = kv0;
        Vw[vec * 33 + d] = vv0;
    }
    // stage learnable tokens (transposed to [l][d])
    if (tid < 288) {
        int d = tid / 9, l = tid - d * 9;
        lts[l * 33 + d] = lt[hh * 288 + tid];
    }
    int n = ntile * 32 + w;
    size_t qoff = ((size_t)(b * NTOK + n)) * 256 + hh * 32 + lane;
    qss[w * 33 + lane] = g_qs[qoff];
    qns[w * 33 + lane] = g_q[qoff];
    __syncthreads();

    int xl = n & 31;
    const int* rix = rel_idx + (size_t)n * 64;
    // 82 outputs: 0..8 local logits, 9..72 pool logits, 73..81 learnable corr
#pragma unroll
    for (int oi = 0; oi < 3; oi++) {
        int o = lane + oi * 32;
        if (o < 82) {
            const float* kr;
            const float* qr;
            float bias;
            if (o < 9) {
                int r = o / 3, dc = o - r * 3;
                kr = Kw + (r * 34 + xl + dc) * 33;
                qr = qss + w * 33;
                bias = rpb[hh * 9 + o];
            } else if (o < 73) {
                int p = o - 9;
                kr = kp + p * 33;
                qr = qss + w * 33;
                bias = g_cpb[(size_t)rix[p] * 8 + hh];
            } else {
                int l = o - 73;
                kr = lts + l * 33;
                qr = qns + w * 33;
                bias = lb[hh * 9 + l];
            }
            float acc = bias;
#pragma unroll
            for (int d = 0; d < 32; d++) acc += qr[d] * kr[d];
            lg[w * 84 + o] = acc;
        }
    }
    __syncwarp();
    // softmax over 73 logits
    float v0 = lg[w * 84 + lane];
    float v1 = lg[w * 84 + lane + 32];
    float v2 = (lane < 9) ? lg[w * 84 + lane + 64] : -3.4e38f;
    float mx = warp_max(fmaxf(fmaxf(v0, v1), v2));
    float e0 = expf(v0 - mx), e1 = expf(v1 - mx);
    float e2 = (lane < 9) ? expf(v2 - mx) : 0.f;
    float inv = 1.0f / warp_sum(e0 + e1 + e2);
    // local coeff = prob + learnable correction (stored at 73..81)
    lg[w * 84 + lane] = e0 * inv + ((lane < 9) ? lg[w * 84 + 73 + lane] : 0.f);
    lg[w * 84 + lane + 32] = e1 * inv;
    if (lane < 9) lg[w * 84 + lane + 64] = e2 * inv;
    __syncwarp();
    // AV accumulation (lane = d)
    float outv = 0.f;
#pragma unroll
    for (int l = 0; l < 9; l++) {
        int r = l / 3, dc = l - r * 3;
        outv += lg[w * 84 + l] * Vw[(r * 34 + xl + dc) * 33 + lane];
    }
#pragma unroll 8
    for (int p = 0; p < 64; p++)
        outv += lg[w * 84 + 9 + p] * vp[p * 33 + lane];
    float gt = g_gate[((size_t)(b * NTOK + n)) * 8 + hh];
    float val = outv * gt;
    __nv_bfloat16 vh = __float2bfloat16(val);
    size_t oidx = ((size_t)(b * NTOK + n)) * 256 + hh * 32 + lane;
    g_ah[oidx] = vh;
    g_al[oidx] = __float2bfloat16(val - __bfloat162float(vh));
}

// ---------------- launch ----------------------------------------------------
extern "C" void kernel_launch(void* const* d_in, const int* in_sizes, int n_in,
                              void* d_out, int out_size) {
    const float* x      = (const float*)d_in[0];
    const float* rct    = (const float*)d_in[1];
    const float* q_w    = (const float*)d_in[2];
    const float* q_b    = (const float*)d_in[3];
    const float* kv_w   = (const float*)d_in[4];
    const float* kv_b   = (const float*)d_in[5];
    const float* temp   = (const float*)d_in[6];
    const float* qe     = (const float*)d_in[7];
    const float* rpb    = (const float*)d_in[8];
    const float* lt     = (const float*)d_in[9];
    const float* lb     = (const float*)d_in[10];
    const float* cpb1_w = (const float*)d_in[11];
    const float* cpb1_b = (const float*)d_in[12];
    const float* cpb2_w = (const float*)d_in[13];
    const float* cpb2_b = (const float*)d_in[14];
    const float* sr_w   = (const float*)d_in[15];
    const float* sr_b   = (const float*)d_in[16];
    const float* norm_g = (const float*)d_in[17];
    const float* norm_b = (const float*)d_in[18];
    const float* wg_w   = (const float*)d_in[19];
    const float* wg0_w  = (const float*)d_in[20];
    const float* wg1_w  = (const float*)d_in[21];
    const float* proj_w = (const float*)d_in[22];
    const float* proj_b = (const float*)d_in[23];
    const int*   ridx   = (const int*)d_in[24];
    float* out = (float*)d_out;

    float *pq, *pkv, *psr, *pkvp;
    __nv_bfloat16 *pxh, *pxl, *pwh, *pwl, *pph, *ppl, *pah, *pal;
    cudaGetSymbolAddress((void**)&pq,  g_q);
    cudaGetSymbolAddress((void**)&pkv, g_kv);
    cudaGetSymbolAddress((void**)&psr, g_sr);
    cudaGetSymbolAddress((void**)&pkvp, g_kvp);
    cudaGetSymbolAddress((void**)&pxh, g_xh);
    cudaGetSymbolAddress((void**)&pxl, g_xl);
    cudaGetSymbolAddress((void**)&pwh, g_wh);
    cudaGetSymbolAddress((void**)&pwl, g_wl);
    cudaGetSymbolAddress((void**)&pph, g_ph);
    cudaGetSymbolAddress((void**)&ppl, g_pl);
    cudaGetSymbolAddress((void**)&pah, g_ah);
    cudaGetSymbolAddress((void**)&pal, g_al);

    cudaFuncSetAttribute(gemm_bf16<0>,
                         cudaFuncAttributeMaxDynamicSharedMemorySize, GSMEM);
    cudaFuncSetAttribute(gemm_bf16<1>,
                         cudaFuncAttributeMaxDynamicSharedMemorySize, GSMEM);
    cudaFuncSetAttribute(attn_kernel,
                         cudaFuncAttributeMaxDynamicSharedMemorySize, ASMEMB);

    const int M = BATCH * NTOK;                       // 16384

    conv_x_gate<<<M / 8, 256>>>(x, wg_w, wg0_w, wg1_w);
    conv_w<<<320, 256>>>(q_w, kv_w, sr_w, proj_w);

    dim3 gf(8, M / 128);
    gemm_bf16<0><<<gf, 256, GSMEM>>>(pxh, pxl, pwh, pwl,
                                     pq, pkv, psr, q_b, kv_b, sr_b, 0);
    q_post<<<M, 256>>>(temp, qe);
    kv_post<<<M, 256>>>();
    pool_ln<<<BATCH * PLP, 256>>>(norm_g, norm_b);
    dim3 gp(4, 2);
    gemm_bf16<1><<<gp, 256, GSMEM>>>(pph, ppl, pwh + 256 * 256, pwl + 256 * 256,
                                     pkvp, nullptr, nullptr, kv_b, nullptr,
                                     nullptr, 512);
    kvpool_post<<<BATCH * PLP, 256>>>();
    cpb_kernel<<<TBLN, 128>>>(rct, cpb1_w, cpb1_b, cpb2_w, cpb2_b);
    attn_kernel<<<BATCH * NH * (NTOK / 32), 1024, ASMEMB>>>(rpb, lt, lb, ridx);
    dim3 gj(2, M / 128);
    gemm_bf16<1><<<gj, 256, GSMEM>>>(pah, pal, pwh + 1024 * 256, pwl + 1024 * 256,
                                     out, nullptr, nullptr, proj_b, nullptr,
                                     nullptr, 256);
}

// round 7
// speedup vs baseline: 1.1437x; 1.1371x over previous
#include <cuda_runtime.h>
#include <cuda_bf16.h>
#include <cuda_fp16.h>
#include <math.h>
#include <stdint.h>

#define BATCH 4
#define NTOK  4096      // N = 64*64
#define CDIM  256
#define NH    8
#define HD    32
#define RESHW 64
#define PLP   64        // pooled length (8*8)
#define TBLN  4096
#define EPSF  1.1920929e-07f

// ---------------- scratch (device globals; no dynamic alloc) ----------------
__device__ float g_q   [BATCH*NTOK*CDIM];
__device__ float g_qs  [BATCH*NTOK*CDIM];
__device__ float g_kv  [BATCH*NTOK*2*CDIM];
__device__ float g_sr  [BATCH*NTOK*CDIM];
__device__ float g_gate[BATCH*NTOK*NH];
__device__ float g_kvp [BATCH*PLP*2*CDIM];
__device__ float g_cpb [TBLN*NH];
__device__ __half g_xh [BATCH*NTOK*CDIM];        // x as fp16 (A side, single)
__device__ __half g_wh [1280*CDIM];              // weights hi: q(0) kv(256) sr(768) proj(1024)
__device__ __half g_wl [1280*CDIM];              // weights lo
__device__ __half g_ph [BATCH*PLP*CDIM];         // pooled+LN fp16
__device__ __half g_ah [BATCH*NTOK*CDIM];        // attention out fp16

__device__ __forceinline__ float warp_sum(float v) {
#pragma unroll
    for (int o = 16; o; o >>= 1) v += __shfl_xor_sync(0xffffffffu, v, o);
    return v;
}
__device__ __forceinline__ float warp_max(float v) {
#pragma unroll
    for (int o = 16; o; o >>= 1) v = fmaxf(v, __shfl_xor_sync(0xffffffffu, v, o));
    return v;
}

// ================= helpers ==================================================
__device__ __forceinline__ uint32_t smem_u32(const void* p) {
    uint32_t a;
    asm("{ .reg .u64 t; cvta.to.shared.u64 t, %1; cvt.u32.u64 %0, t; }"
        : "=r"(a) : "l"(p));
    return a;
}
__device__ __forceinline__ void ldsm_x4(uint32_t* r, uint32_t addr) {
    asm volatile("ldmatrix.sync.aligned.m8n8.x4.shared.b16 {%0,%1,%2,%3}, [%4];"
                 : "=r"(r[0]), "=r"(r[1]), "=r"(r[2]), "=r"(r[3]) : "r"(addr));
}
__device__ __forceinline__ void ldsm_x2(uint32_t* r, uint32_t addr) {
    asm volatile("ldmatrix.sync.aligned.m8n8.x2.shared.b16 {%0,%1}, [%2];"
                 : "=r"(r[0]), "=r"(r[1]) : "r"(addr));
}
__device__ __forceinline__ void mma_f16(float* c, const uint32_t* a,
                                        const uint32_t* b) {
    asm volatile(
        "mma.sync.aligned.m16n8k16.row.col.f32.f16.f16.f32 "
        "{%0,%1,%2,%3}, {%4,%5,%6,%7}, {%8,%9}, {%0,%1,%2,%3};"
        : "+f"(c[0]), "+f"(c[1]), "+f"(c[2]), "+f"(c[3])
        : "r"(a[0]), "r"(a[1]), "r"(a[2]), "r"(a[3]), "r"(b[0]), "r"(b[1]));
}
__device__ __forceinline__ void cp16(uint32_t dst, const void* src) {
    asm volatile("cp.async.cg.shared.global [%0], [%1], 16;"
                 :: "r"(dst), "l"(src));
}
#define CP_COMMIT() asm volatile("cp.async.commit_group;" ::: "memory")
#define CP_WAIT0()  asm volatile("cp.async.wait_group 0;" ::: "memory")

// ---------------- x convert (fp16) + gating (single x read) ------------------
__global__ void __launch_bounds__(256)
conv_x_gate(const float* __restrict__ x, const float* __restrict__ wg,
            const float* __restrict__ wg0, const float* __restrict__ wg1) {
    int t = blockIdx.x * 8 + (threadIdx.x >> 5);
    int lane = threadIdx.x & 31;
    const float* xt = x + (size_t)t * CDIM;
    float4 xa = *(const float4*)(xt + lane * 8);
    float4 xb = *(const float4*)(xt + lane * 8 + 4);
    __half2 h0 = __floats2half2_rn(xa.x, xa.y);
    __half2 h1 = __floats2half2_rn(xa.z, xa.w);
    __half2 h2 = __floats2half2_rn(xb.x, xb.y);
    __half2 h3 = __floats2half2_rn(xb.z, xb.w);
    uint4 u;
    u.x = *(uint32_t*)&h0; u.y = *(uint32_t*)&h1;
    u.z = *(uint32_t*)&h2; u.w = *(uint32_t*)&h3;
    *(uint4*)(g_xh + (size_t)t * CDIM + lane * 8) = u;
    float d[10];
#pragma unroll
    for (int i = 0; i < 10; i++) {
        const float* wr = (i < 4) ? wg + i * CDIM
                        : (i < 8) ? wg1 + (i - 4) * CDIM
                                  : wg0 + (i - 8) * CDIM;
        float4 wa = *(const float4*)(wr + lane * 8);
        float4 wb = *(const float4*)(wr + lane * 8 + 4);
        float s = xa.x * wa.x + xa.y * wa.y + xa.z * wa.z + xa.w * wa.w
                + xb.x * wb.x + xb.y * wb.y + xb.z * wb.z + xb.w * wb.w;
        d[i] = warp_sum(s);
    }
    float m0 = fmaxf(fmaxf(d[0], d[1]), fmaxf(d[2], d[3]));
    float e[4], se = 0.f;
#pragma unroll
    for (int i = 0; i < 4; i++) { e[i] = expf(d[i] - m0); se += e[i]; }
    float gsm[4];
#pragma unroll
    for (int i = 0; i < 4; i++) gsm[i] = e[i] / se;
    int i1 = 0;
#pragma unroll
    for (int i = 1; i < 4; i++) if (gsm[i] > gsm[i1]) i1 = i;
    int i2 = -1;
#pragma unroll
    for (int i = 0; i < 4; i++) {
        if (i == i1) continue;
        if (i2 < 0 || gsm[i] > gsm[i2]) i2 = i;
    }
    float rs = fmaxf(gsm[i1] + gsm[i2], EPSF);
    float routed[4];
#pragma unroll
    for (int i = 0; i < 4; i++)
        routed[i] = (i == i1 || i == i2) ? gsm[i] / rs * 2.f : 0.f;
    float m1 = fmaxf(fmaxf(d[4], d[5]), fmaxf(d[6], d[7]));
    float es[4], ss = 0.f;
#pragma unroll
    for (int i = 0; i < 4; i++) { es[i] = expf(d[4 + i] - m1); ss += es[i]; }
    float shg[4];
#pragma unroll
    for (int i = 0; i < 4; i++) shg[i] = es[i] / ss * 4.f;
    float m2 = fmaxf(d[8], d[9]);
    float e8 = expf(d[8] - m2), e9 = expf(d[9] - m2);
    float w00 = e8 / (e8 + e9) * 2.f;
    float w01 = e9 / (e8 + e9) * 2.f;
    if (lane < NH) {
        float v = (lane < 4) ? w00 * shg[lane] : w01 * routed[lane - 4];
        g_gate[(size_t)t * NH + lane] = v;
    }
}

// ---------------- all-weights fp16 hi/lo convert (one launch) ----------------
__global__ void __launch_bounds__(256)
conv_w(const float* __restrict__ qw, const float* __restrict__ kvw,
       const float* __restrict__ srw, const float* __restrict__ pjw) {
    int i = blockIdx.x * 256 + threadIdx.x;   // float4 index, 81920 total
    int row = i >> 6;
    const float4* src;
    int off;
    if (row < 256)       { src = (const float4*)qw;  off = i; }
    else if (row < 768)  { src = (const float4*)kvw; off = i - 256 * 64; }
    else if (row < 1024) { src = (const float4*)srw; off = i - 768 * 64; }
    else                 { src = (const float4*)pjw; off = i - 1024 * 64; }
    float4 v = src[off];
    __half a0 = __float2half_rn(v.x), a1 = __float2half_rn(v.y);
    __half a2 = __float2half_rn(v.z), a3 = __float2half_rn(v.w);
    __half b0 = __float2half_rn(v.x - __half2float(a0));
    __half b1 = __float2half_rn(v.y - __half2float(a1));
    __half b2 = __float2half_rn(v.z - __half2float(a2));
    __half b3 = __float2half_rn(v.w - __half2float(a3));
    ushort4 H, L;
    H.x = *(uint16_t*)&a0; H.y = *(uint16_t*)&a1;
    H.z = *(uint16_t*)&a2; H.w = *(uint16_t*)&a3;
    L.x = *(uint16_t*)&b0; L.y = *(uint16_t*)&b1;
    L.z = *(uint16_t*)&b2; L.w = *(uint16_t*)&b3;
    ((ushort4*)g_wh)[i] = H;
    ((ushort4*)g_wl)[i] = L;
}

// ================= double-buffered 2-term fp16 GEMM =========================
// C = A[*,256] @ (Wh+Wl)[*,256]^T + bias. Tile 128x128, 8 warps.
#define MATSZ (128 * 40)
#define GSMEM (2 * 3 * MATSZ * 2)   // 61440 B

template<int MODE>
__global__ void __launch_bounds__(256)
gemm_f16(const __half* __restrict__ A,
         const __half* __restrict__ Wh, const __half* __restrict__ Wl,
         float* __restrict__ C0, float* __restrict__ C1, float* __restrict__ C2,
         const float* __restrict__ b0, const float* __restrict__ b1,
         const float* __restrict__ b2, int ldc0) {
    extern __shared__ uint16_t sd[];
    const int bm = blockIdx.y * 128, bn = blockIdx.x * 128;
    const int tid = threadIdx.x, lane = tid & 31, wid = tid >> 5;
    const int wm = (wid & 3) * 32, wn = (wid >> 2) * 64;
    float acc[2][8][4] = {};

    const __half* gsrc[3] = {
        A + (size_t)bm * 256, Wh + (size_t)bn * 256, Wl + (size_t)bn * 256};

#pragma unroll
    for (int m = 0; m < 3; m++)
#pragma unroll
        for (int s = 0; s < 2; s++) {
            int seg = tid + s * 256;
            int row = seg >> 2, part = seg & 3;
            cp16(smem_u32(sd + m * MATSZ + row * 40 + part * 8),
                 gsrc[m] + (size_t)row * 256 + part * 8);
        }
    CP_COMMIT();

    for (int kc = 0; kc < 8; kc++) {
        const int stg = kc & 1;
        CP_WAIT0();
        __syncthreads();
        if (kc < 7) {
            const int nb = (stg ^ 1) * 3 * MATSZ;
            const int ko = (kc + 1) * 32;
#pragma unroll
            for (int m = 0; m < 3; m++)
#pragma unroll
                for (int s = 0; s < 2; s++) {
                    int seg = tid + s * 256;
                    int row = seg >> 2, part = seg & 3;
                    cp16(smem_u32(sd + nb + m * MATSZ + row * 40 + part * 8),
                         gsrc[m] + (size_t)row * 256 + ko + part * 8);
                }
            CP_COMMIT();
        }
        uint16_t* pA  = sd + (stg * 3 + 0) * MATSZ;
        uint16_t* pBh = sd + (stg * 3 + 1) * MATSZ;
        uint16_t* pBl = sd + (stg * 3 + 2) * MATSZ;
#pragma unroll
        for (int ks = 0; ks < 2; ks++) {
            uint32_t ah[2][4];
            const int arow = lane & 15, acol = ks * 16 + (lane >> 4) * 8;
#pragma unroll
            for (int i = 0; i < 2; i++)
                ldsm_x4(ah[i], smem_u32(pA + (wm + i * 16 + arow) * 40 + acol));
            const int brow0 = wn + (lane & 7);
            const int bcol = ks * 16 + ((lane >> 3) & 1) * 8;
#pragma unroll
            for (int j = 0; j < 8; j++) {
                uint32_t bh[2], bl[2];
                ldsm_x2(bh, smem_u32(pBh + (brow0 + j * 8) * 40 + bcol));
                ldsm_x2(bl, smem_u32(pBl + (brow0 + j * 8) * 40 + bcol));
#pragma unroll
                for (int i = 0; i < 2; i++) {
                    mma_f16(acc[i][j], ah[i], bh);
                    mma_f16(acc[i][j], ah[i], bl);
                }
            }
        }
    }
    float* C; const float* bias; int ldc, cb, act = 0;
    if (MODE == 0) {
        int r = bn >> 7;
        if (r < 2)      { C = C0; bias = b0; ldc = 256; cb = bn; }
        else if (r < 6) { C = C1; bias = b1; ldc = 512; cb = bn - 256; }
        else            { C = C2; bias = b2; ldc = 256; cb = bn - 768; act = 1; }
    } else {
        C = C0; bias = b0; ldc = ldc0; cb = bn;
    }
#pragma unroll
    for (int i = 0; i < 2; i++) {
        int r0 = bm + wm + i * 16 + (lane >> 2);
#pragma unroll
        for (int j = 0; j < 8; j++) {
            int col = cb + wn + j * 8 + (lane & 3) * 2;
            float bb0 = bias[col], bb1 = bias[col + 1];
            float v0 = acc[i][j][0] + bb0, v1 = acc[i][j][1] + bb1;
            float v2 = acc[i][j][2] + bb0, v3 = acc[i][j][3] + bb1;
            if (MODE == 0 && act) {
                v0 = 0.5f * v0 * (1.0f + erff(v0 * 0.70710678118654752f));
                v1 = 0.5f * v1 * (1.0f + erff(v1 * 0.70710678118654752f));
                v2 = 0.5f * v2 * (1.0f + erff(v2 * 0.70710678118654752f));
                v3 = 0.5f * v3 * (1.0f + erff(v3 * 0.70710678118654752f));
            }
            float2 o01; o01.x = v0; o01.y = v1;
            float2 o23; o23.x = v2; o23.y = v3;
            *(float2*)(C + (size_t)r0 * ldc + col) = o01;
            *(float2*)(C + (size_t)(r0 + 8) * ldc + col) = o23;
        }
    }
}

// ---------------- merged q/kv postprocess ------------------------------------
__global__ void __launch_bounds__(256)
qkv_post(const float* __restrict__ temp, const float* __restrict__ qe) {
    int bid = blockIdx.x;
    int h = threadIdx.x >> 5, lane = threadIdx.x & 31;
    if (bid < BATCH * NTOK) {
        int bn = bid;
        int n = bn & (NTOK - 1);
        size_t off = (size_t)bn * CDIM + h * HD + lane;
        float v = g_q[off];
        float nrm = sqrtf(warp_sum(v * v));
        float qn = v / fmaxf(nrm, EPSF);
        int y = n >> 6, x = n & 63;
        int ch = min(y + 1, 63) - max(y - 1, 0) + 1;
        int cw = min(x + 1, 63) - max(x - 1, 0) + 1;
        float sls = logf((float)(ch * cw + PLP));
        float sp = log1pf(expf(temp[h]));
        g_q [off] = qn;
        g_qs[off] = (qn + qe[h * HD + lane]) * sp * sls;
    } else {
        int bn = bid - BATCH * NTOK;
        size_t off = (size_t)bn * 2 * CDIM + h * HD + lane;
        float v = g_kv[off];
        float nrm = sqrtf(warp_sum(v * v));
        g_kv[off] = v / fmaxf(nrm, EPSF);
    }
}

__global__ void __launch_bounds__(256) kvpool_post() {
    int bp = blockIdx.x;
    int h = threadIdx.x >> 5, lane = threadIdx.x & 31;
    size_t off = (size_t)bp * 2 * CDIM + h * HD + lane;
    float v = g_kvp[off];
    float nrm = sqrtf(warp_sum(v * v));
    g_kvp[off] = v / fmaxf(nrm, EPSF);
}

// ---------------- 8x8 avg pool + LayerNorm (writes fp16) ---------------------
__global__ void __launch_bounds__(256)
pool_ln(const float* __restrict__ gw, const float* __restrict__ gb) {
    int bp = blockIdx.x;
    int b = bp >> 6, p = bp & 63;
    int py = p >> 3, px = p & 7;
    int c = threadIdx.x;
    const float* base = g_sr + (size_t)b * NTOK * CDIM;
    float s = 0.f;
    for (int iy = 0; iy < 8; iy++) {
        int y = py * 8 + iy;
        for (int ix = 0; ix < 8; ix++) {
            int n = y * RESHW + px * 8 + ix;
            s += base[(size_t)n * CDIM + c];
        }
    }
    float val = s * (1.0f / 64.0f);
    __shared__ float red[256];
    red[c] = val; __syncthreads();
    for (int st = 128; st > 0; st >>= 1) { if (c < st) red[c] += red[c + st]; __syncthreads(); }
    float mu = red[0] * (1.0f / 256.0f);
    __syncthreads();
    float dv = val - mu;
    red[c] = dv * dv; __syncthreads();
    for (int st = 128; st > 0; st >>= 1) { if (c < st) red[c] += red[c + st]; __syncthreads(); }
    float var = red[0] * (1.0f / 256.0f);
    float ov = dv * rsqrtf(var + 1e-5f) * gw[c] + gb[c];
    g_ph[(size_t)bp * CDIM + c] = __float2half_rn(ov);
}

// ---------------- cpb MLP ----------------------------------------------------
__global__ void __launch_bounds__(128)
cpb_kernel(const float* __restrict__ tbl, const float* __restrict__ w1,
           const float* __restrict__ b1, const float* __restrict__ w2,
           const float* __restrict__ b2) {
    int row = blockIdx.x;
    int tid = threadIdx.x;
    float t0 = tbl[row * 2 + 0], t1 = tbl[row * 2 + 1];
    float acc[8] = {};
    for (int j = tid; j < 512; j += 128) {
        float hv = fmaxf(t0 * w1[2 * j] + t1 * w1[2 * j + 1] + b1[j], 0.f);
#pragma unroll
        for (int o = 0; o < 8; o++) acc[o] += hv * w2[o * 512 + j];
    }
#pragma unroll
    for (int o = 0; o < 8; o++) acc[o] = warp_sum(acc[o]);
    __shared__ float sh[4][8];
    int wp = tid >> 5, lane = tid & 31;
    if (lane == 0)
#pragma unroll
        for (int o = 0; o < 8; o++) sh[wp][o] = acc[o];
    __syncthreads();
    if (tid < 8)
        g_cpb[(size_t)row * 8 + tid] =
            sh[0][tid] + sh[1][tid] + sh[2][tid] + sh[3][tid] + b2[tid];
}

// ---------------- fused attention: lane-serial outputs, smem staging ---------
#define AOKW 0
#define AOVW 3366
#define AOKP 6732
#define AOVP 8844
#define AOQS 10956
#define AOQN 12012
#define AOLG 13068
#define AOLT 15756
#define ASMEMB ((15756 + 9 * 33 + 3) * 4)   // bytes

__global__ void __launch_bounds__(1024)
attn_kernel(const float* __restrict__ rpb, const float* __restrict__ lt,
            const float* __restrict__ lb, const int* __restrict__ rel_idx) {
    extern __shared__ float sh[];
    float* Kw  = sh + AOKW;    // [102][33]
    float* Vw  = sh + AOVW;
    float* kp  = sh + AOKP;    // [64][33]
    float* vp  = sh + AOVP;
    float* qss = sh + AOQS;    // [32][33]
    float* qns = sh + AOQN;
    float* lg  = sh + AOLG;    // [32][84]
    float* lts = sh + AOLT;    // [9][33]
    int blk = blockIdx.x;
    int ntile = blk & 127;
    int hh = (blk >> 7) & 7;
    int b = blk >> 10;
    int tid = threadIdx.x, w = tid >> 5, lane = tid & 31;
    int y = ntile >> 1, x0 = (ntile & 1) << 5;

    for (int i = tid; i < 2048; i += 1024) {
        int p = i >> 5, d = i & 31;
        size_t base = ((size_t)(b * PLP + p)) * 512 + hh * 32 + d;
        kp[p * 33 + d] = g_kvp[base];
        vp[p * 33 + d] = g_kvp[base + 256];
    }
    for (int i = tid; i < 3264; i += 1024) {
        int vec = i >> 5, d = i & 31;
        int r = vec / 34, c = vec - r * 34;
        int yy = y + r - 1, xx = x0 - 1 + c;
        float kv0 = 0.f, vv0 = 0.f;
        if ((unsigned)yy < 64u && (unsigned)xx < 64u) {
            size_t base = ((size_t)(b * NTOK + yy * 64 + xx)) * 512 + hh * 32 + d;
            kv0 = g_kv[base];
            vv0 = g_kv[base + 256];
        }
        Kw[vec * 33 + d] = kv0;
        Vw[vec * 33 + d] = vv0;
    }
    if (tid < 288) {
        int d = tid / 9, l = tid - d * 9;
        lts[l * 33 + d] = lt[hh * 288 + tid];
    }
    int n = ntile * 32 + w;
    size_t qoff = ((size_t)(b * NTOK + n)) * 256 + hh * 32 + lane;
    qss[w * 33 + lane] = g_qs[qoff];
    qns[w * 33 + lane] = g_q[qoff];
    __syncthreads();

    int xl = n & 31;
    const int* rix = rel_idx + (size_t)n * 64;
#pragma unroll
    for (int oi = 0; oi < 3; oi++) {
        int o = lane + oi * 32;
        if (o < 82) {
            const float* kr;
            const float* qr;
            float bias;
            if (o < 9) {
                int r = o / 3, dc = o - r * 3;
                kr = Kw + (r * 34 + xl + dc) * 33;
                qr = qss + w * 33;
                bias = rpb[hh * 9 + o];
            } else if (o < 73) {
                int p = o - 9;
                kr = kp + p * 33;
                qr = qss + w * 33;
                bias = g_cpb[(size_t)rix[p] * 8 + hh];
            } else {
                int l = o - 73;
                kr = lts + l * 33;
                qr = qns + w * 33;
                bias = lb[hh * 9 + l];
            }
            float acc = bias;
#pragma unroll
            for (int d = 0; d < 32; d++) acc += qr[d] * kr[d];
            lg[w * 84 + o] = acc;
        }
    }
    __syncwarp();
    float v0 = lg[w * 84 + lane];
    float v1 = lg[w * 84 + lane + 32];
    float v2 = (lane < 9) ? lg[w * 84 + lane + 64] : -3.4e38f;
    float mx = warp_max(fmaxf(fmaxf(v0, v1), v2));
    float e0 = expf(v0 - mx), e1 = expf(v1 - mx);
    float e2 = (lane < 9) ? expf(v2 - mx) : 0.f;
    float inv = 1.0f / warp_sum(e0 + e1 + e2);
    lg[w * 84 + lane] = e0 * inv + ((lane < 9) ? lg[w * 84 + 73 + lane] : 0.f);
    lg[w * 84 + lane + 32] = e1 * inv;
    if (lane < 9) lg[w * 84 + lane + 64] = e2 * inv;
    __syncwarp();
    float outv = 0.f;
#pragma unroll
    for (int l = 0; l < 9; l++) {
        int r = l / 3, dc = l - r * 3;
        outv += lg[w * 84 + l] * Vw[(r * 34 + xl + dc) * 33 + lane];
    }
#pragma unroll 8
    for (int p = 0; p < 64; p++)
        outv += lg[w * 84 + 9 + p] * vp[p * 33 + lane];
    float gt = g_gate[((size_t)(b * NTOK + n)) * 8 + hh];
    g_ah[((size_t)(b * NTOK + n)) * 256 + hh * 32 + lane] =
        __float2half_rn(outv * gt);
}

// ---------------- launch ----------------------------------------------------
extern "C" void kernel_launch(void* const* d_in, const int* in_sizes, int n_in,
                              void* d_out, int out_size) {
    const float* x      = (const float*)d_in[0];
    const float* rct    = (const float*)d_in[1];
    const float* q_w    = (const float*)d_in[2];
    const float* q_b    = (const float*)d_in[3];
    const float* kv_w   = (const float*)d_in[4];
    const float* kv_b   = (const float*)d_in[5];
    const float* temp   = (const float*)d_in[6];
    const float* qe     = (const float*)d_in[7];
    const float* rpb    = (const float*)d_in[8];
    const float* lt     = (const float*)d_in[9];
    const float* lb     = (const float*)d_in[10];
    const float* cpb1_w = (const float*)d_in[11];
    const float* cpb1_b = (const float*)d_in[12];
    const float* cpb2_w = (const float*)d_in[13];
    const float* cpb2_b = (const float*)d_in[14];
    const float* sr_w   = (const float*)d_in[15];
    const float* sr_b   = (const float*)d_in[16];
    const float* norm_g = (const float*)d_in[17];
    const float* norm_b = (const float*)d_in[18];
    const float* wg_w   = (const float*)d_in[19];
    const float* wg0_w  = (const float*)d_in[20];
    const float* wg1_w  = (const float*)d_in[21];
    const float* proj_w = (const float*)d_in[22];
    const float* proj_b = (const float*)d_in[23];
    const int*   ridx   = (const int*)d_in[24];
    float* out = (float*)d_out;

    float *pq, *pkv, *psr, *pkvp;
    __half *pxh, *pwh, *pwl, *pph, *pah;
    cudaGetSymbolAddress((void**)&pq,   g_q);
    cudaGetSymbolAddress((void**)&pkv,  g_kv);
    cudaGetSymbolAddress((void**)&psr,  g_sr);
    cudaGetSymbolAddress((void**)&pkvp, g_kvp);
    cudaGetSymbolAddress((void**)&pxh,  g_xh);
    cudaGetSymbolAddress((void**)&pwh,  g_wh);
    cudaGetSymbolAddress((void**)&pwl,  g_wl);
    cudaGetSymbolAddress((void**)&pph,  g_ph);
    cudaGetSymbolAddress((void**)&pah,  g_ah);

    cudaFuncSetAttribute(gemm_f16<0>,
                         cudaFuncAttributeMaxDynamicSharedMemorySize, GSMEM);
    cudaFuncSetAttribute(gemm_f16<1>,
                         cudaFuncAttributeMaxDynamicSharedMemorySize, GSMEM);
    cudaFuncSetAttribute(attn_kernel,
                         cudaFuncAttributeMaxDynamicSharedMemorySize, ASMEMB);

    const int M = BATCH * NTOK;                       // 16384

    // launch idx:                                    // profiled slot = idx 3
    conv_x_gate<<<M / 8, 256>>>(x, wg_w, wg0_w, wg1_w);          // 0
    conv_w<<<320, 256>>>(q_w, kv_w, sr_w, proj_w);               // 1
    cpb_kernel<<<TBLN, 128>>>(rct, cpb1_w, cpb1_b, cpb2_w, cpb2_b); // 2
    dim3 gf(8, M / 128);
    gemm_f16<0><<<gf, 256, GSMEM>>>(pxh, pwh, pwl,               // 3 (profiled)
                                    pq, pkv, psr, q_b, kv_b, sr_b, 0);
    qkv_post<<<2 * M, 256>>>(temp, qe);                          // 4
    pool_ln<<<BATCH * PLP, 256>>>(norm_g, norm_b);               // 5
    dim3 gp(4, 2);
    gemm_f16<1><<<gp, 256, GSMEM>>>(pph, pwh + 256 * 256, pwl + 256 * 256,
                                    pkvp, nullptr, nullptr, kv_b, nullptr,
                                    nullptr, 512);               // 6
    kvpool_post<<<BATCH * PLP, 256>>>();                         // 7
    attn_kernel<<<BATCH * NH * (NTOK / 32), 1024, ASMEMB>>>(rpb, lt, lb, ridx); // 8
    dim3 gj(2, M / 128);
    gemm_f16<1><<<gj, 256, GSMEM>>>(pah, pwh + 1024 * 256, pwl + 1024 * 256,
                                    out, nullptr, nullptr, proj_b, nullptr,
                                    nullptr, 256);               // 9
}

// round 8
// speedup vs baseline: 1.4575x; 1.2743x over previous
#include <cuda_runtime.h>
#include <cuda_bf16.h>
#include <cuda_fp16.h>
#include <math.h>
#include <stdint.h>

#define BATCH 4
#define NTOK  4096      // N = 64*64
#define CDIM  256
#define NH    8
#define HD    32
#define RESHW 64
#define PLP   64        // pooled length (8*8)
#define TBLN  4096
#define BH    (BATCH*NH)
#define EPSF  1.1920929e-07f

// ---------------- scratch (device globals; no dynamic alloc) ----------------
__device__ float g_q   [BATCH*NTOK*CDIM];        // q_norm fp32
__device__ float g_kv  [BATCH*NTOK*2*CDIM];      // kv; k half normalized
__device__ float g_sr  [BATCH*NTOK*CDIM];
__device__ float g_gate[BATCH*NTOK*NH];
__device__ float g_kvp [BATCH*PLP*2*CDIM];
__device__ float g_cpb [TBLN*NH];
__device__ __half g_xh [BATCH*NTOK*CDIM];        // x fp16
__device__ __half g_wh [1280*CDIM];              // weights hi
__device__ __half g_wl [1280*CDIM];              // weights lo
__device__ __half g_ph [BATCH*PLP*CDIM];         // pooled+LN fp16
__device__ __half g_ah [BATCH*NTOK*CDIM];        // attention out fp16
__device__ __half g_qsh[BATCH*NTOK*CDIM];        // q_scaled hi
__device__ __half g_qsl[BATCH*NTOK*CDIM];        // q_scaled lo
__device__ __half g_kph[BATCH*PLP*CDIM];         // k_pool norm hi
__device__ __half g_kpl[BATCH*PLP*CDIM];         // k_pool norm lo
__device__ __half g_vph[BATCH*PLP*CDIM];         // v_pool fp16
__device__ float  g_spool[BH*NTOK*PLP];          // pool logits
__device__ __half g_ph2[BH*NTOK*PLP];            // pool probs hi
__device__ __half g_pl2[BH*NTOK*PLP];            // pool probs lo
__device__ float  g_lout[BH*NTOK*HD];            // local partial out

__device__ __forceinline__ float warp_sum(float v) {
#pragma unroll
    for (int o = 16; o; o >>= 1) v += __shfl_xor_sync(0xffffffffu, v, o);
    return v;
}
__device__ __forceinline__ float warp_max(float v) {
#pragma unroll
    for (int o = 16; o; o >>= 1) v = fmaxf(v, __shfl_xor_sync(0xffffffffu, v, o));
    return v;
}

// ================= helpers ==================================================
__device__ __forceinline__ uint32_t smem_u32(const void* p) {
    uint32_t a;
    asm("{ .reg .u64 t; cvta.to.shared.u64 t, %1; cvt.u32.u64 %0, t; }"
        : "=r"(a) : "l"(p));
    return a;
}
__device__ __forceinline__ void ldsm_x4(uint32_t* r, uint32_t addr) {
    asm volatile("ldmatrix.sync.aligned.m8n8.x4.shared.b16 {%0,%1,%2,%3}, [%4];"
                 : "=r"(r[0]), "=r"(r[1]), "=r"(r[2]), "=r"(r[3]) : "r"(addr));
}
__device__ __forceinline__ void ldsm_x2(uint32_t* r, uint32_t addr) {
    asm volatile("ldmatrix.sync.aligned.m8n8.x2.shared.b16 {%0,%1}, [%2];"
                 : "=r"(r[0]), "=r"(r[1]) : "r"(addr));
}
__device__ __forceinline__ void mma_f16(float* c, const uint32_t* a,
                                        const uint32_t* b) {
    asm volatile(
        "mma.sync.aligned.m16n8k16.row.col.f32.f16.f16.f32 "
        "{%0,%1,%2,%3}, {%4,%5,%6,%7}, {%8,%9}, {%0,%1,%2,%3};"
        : "+f"(c[0]), "+f"(c[1]), "+f"(c[2]), "+f"(c[3])
        : "r"(a[0]), "r"(a[1]), "r"(a[2]), "r"(a[3]), "r"(b[0]), "r"(b[1]));
}
__device__ __forceinline__ void cp16(uint32_t dst, const void* src) {
    asm volatile("cp.async.cg.shared.global [%0], [%1], 16;"
                 :: "r"(dst), "l"(src));
}
#define CP_COMMIT() asm volatile("cp.async.commit_group;" ::: "memory")
#define CP_WAIT0()  asm volatile("cp.async.wait_group 0;" ::: "memory")

// ---------------- x convert (fp16) + gating (single x read) ------------------
__global__ void __launch_bounds__(256)
conv_x_gate(const float* __restrict__ x, const float* __restrict__ wg,
            const float* __restrict__ wg0, const float* __restrict__ wg1) {
    int t = blockIdx.x * 8 + (threadIdx.x >> 5);
    int lane = threadIdx.x & 31;
    const float* xt = x + (size_t)t * CDIM;
    float4 xa = *(const float4*)(xt + lane * 8);
    float4 xb = *(const float4*)(xt + lane * 8 + 4);
    __half2 h0 = __floats2half2_rn(xa.x, xa.y);
    __half2 h1 = __floats2half2_rn(xa.z, xa.w);
    __half2 h2 = __floats2half2_rn(xb.x, xb.y);
    __half2 h3 = __floats2half2_rn(xb.z, xb.w);
    uint4 u;
    u.x = *(uint32_t*)&h0; u.y = *(uint32_t*)&h1;
    u.z = *(uint32_t*)&h2; u.w = *(uint32_t*)&h3;
    *(uint4*)(g_xh + (size_t)t * CDIM + lane * 8) = u;
    float d[10];
#pragma unroll
    for (int i = 0; i < 10; i++) {
        const float* wr = (i < 4) ? wg + i * CDIM
                        : (i < 8) ? wg1 + (i - 4) * CDIM
                                  : wg0 + (i - 8) * CDIM;
        float4 wa = *(const float4*)(wr + lane * 8);
        float4 wb = *(const float4*)(wr + lane * 8 + 4);
        float s = xa.x * wa.x + xa.y * wa.y + xa.z * wa.z + xa.w * wa.w
                + xb.x * wb.x + xb.y * wb.y + xb.z * wb.z + xb.w * wb.w;
        d[i] = warp_sum(s);
    }
    float m0 = fmaxf(fmaxf(d[0], d[1]), fmaxf(d[2], d[3]));
    float e[4], se = 0.f;
#pragma unroll
    for (int i = 0; i < 4; i++) { e[i] = expf(d[i] - m0); se += e[i]; }
    float gsm[4];
#pragma unroll
    for (int i = 0; i < 4; i++) gsm[i] = e[i] / se;
    int i1 = 0;
#pragma unroll
    for (int i = 1; i < 4; i++) if (gsm[i] > gsm[i1]) i1 = i;
    int i2 = -1;
#pragma unroll
    for (int i = 0; i < 4; i++) {
        if (i == i1) continue;
        if (i2 < 0 || gsm[i] > gsm[i2]) i2 = i;
    }
    float rs = fmaxf(gsm[i1] + gsm[i2], EPSF);
    float routed[4];
#pragma unroll
    for (int i = 0; i < 4; i++)
        routed[i] = (i == i1 || i == i2) ? gsm[i] / rs * 2.f : 0.f;
    float m1 = fmaxf(fmaxf(d[4], d[5]), fmaxf(d[6], d[7]));
    float es[4], ss = 0.f;
#pragma unroll
    for (int i = 0; i < 4; i++) { es[i] = expf(d[4 + i] - m1); ss += es[i]; }
    float shg[4];
#pragma unroll
    for (int i = 0; i < 4; i++) shg[i] = es[i] / ss * 4.f;
    float m2 = fmaxf(d[8], d[9]);
    float e8 = expf(d[8] - m2), e9 = expf(d[9] - m2);
    float w00 = e8 / (e8 + e9) * 2.f;
    float w01 = e9 / (e8 + e9) * 2.f;
    if (lane < NH) {
        float v = (lane < 4) ? w00 * shg[lane] : w01 * routed[lane - 4];
        g_gate[(size_t)t * NH + lane] = v;
    }
}

// ---------------- all-weights fp16 hi/lo convert -----------------------------
__global__ void __launch_bounds__(256)
conv_w(const float* __restrict__ qw, const float* __restrict__ kvw,
       const float* __restrict__ srw, const float* __restrict__ pjw) {
    int i = blockIdx.x * 256 + threadIdx.x;   // float4 index, 81920 total
    int row = i >> 6;
    const float4* src;
    int off;
    if (row < 256)       { src = (const float4*)qw;  off = i; }
    else if (row < 768)  { src = (const float4*)kvw; off = i - 256 * 64; }
    else if (row < 1024) { src = (const float4*)srw; off = i - 768 * 64; }
    else                 { src = (const float4*)pjw; off = i - 1024 * 64; }
    float4 v = src[off];
    __half a0 = __float2half_rn(v.x), a1 = __float2half_rn(v.y);
    __half a2 = __float2half_rn(v.z), a3 = __float2half_rn(v.w);
    __half b0 = __float2half_rn(v.x - __half2float(a0));
    __half b1 = __float2half_rn(v.y - __half2float(a1));
    __half b2 = __float2half_rn(v.z - __half2float(a2));
    __half b3 = __float2half_rn(v.w - __half2float(a3));
    ushort4 H, L;
    H.x = *(uint16_t*)&a0; H.y = *(uint16_t*)&a1;
    H.z = *(uint16_t*)&a2; H.w = *(uint16_t*)&a3;
    L.x = *(uint16_t*)&b0; L.y = *(uint16_t*)&b1;
    L.z = *(uint16_t*)&b2; L.w = *(uint16_t*)&b3;
    ((ushort4*)g_wh)[i] = H;
    ((ushort4*)g_wl)[i] = L;
}

// ================= double-buffered 2-term fp16 GEMM =========================
#define MATSZ (128 * 40)
#define GSMEM (2 * 3 * MATSZ * 2)   // 61440 B

template<int MODE>
__global__ void __launch_bounds__(256)
gemm_f16(const __half* __restrict__ A,
         const __half* __restrict__ Wh, const __half* __restrict__ Wl,
         float* __restrict__ C0, float* __restrict__ C1, float* __restrict__ C2,
         const float* __restrict__ b0, const float* __restrict__ b1,
         const float* __restrict__ b2, int ldc0) {
    extern __shared__ uint16_t sd[];
    const int bm = blockIdx.y * 128, bn = blockIdx.x * 128;
    const int tid = threadIdx.x, lane = tid & 31, wid = tid >> 5;
    const int wm = (wid & 3) * 32, wn = (wid >> 2) * 64;
    float acc[2][8][4] = {};

    const __half* gsrc[3] = {
        A + (size_t)bm * 256, Wh + (size_t)bn * 256, Wl + (size_t)bn * 256};

#pragma unroll
    for (int m = 0; m < 3; m++)
#pragma unroll
        for (int s = 0; s < 2; s++) {
            int seg = tid + s * 256;
            int row = seg >> 2, part = seg & 3;
            cp16(smem_u32(sd + m * MATSZ + row * 40 + part * 8),
                 gsrc[m] + (size_t)row * 256 + part * 8);
        }
    CP_COMMIT();

    for (int kc = 0; kc < 8; kc++) {
        const int stg = kc & 1;
        CP_WAIT0();
        __syncthreads();
        if (kc < 7) {
            const int nb = (stg ^ 1) * 3 * MATSZ;
            const int ko = (kc + 1) * 32;
#pragma unroll
            for (int m = 0; m < 3; m++)
#pragma unroll
                for (int s = 0; s < 2; s++) {
                    int seg = tid + s * 256;
                    int row = seg >> 2, part = seg & 3;
                    cp16(smem_u32(sd + nb + m * MATSZ + row * 40 + part * 8),
                         gsrc[m] + (size_t)row * 256 + ko + part * 8);
                }
            CP_COMMIT();
        }
        uint16_t* pA  = sd + (stg * 3 + 0) * MATSZ;
        uint16_t* pBh = sd + (stg * 3 + 1) * MATSZ;
        uint16_t* pBl = sd + (stg * 3 + 2) * MATSZ;
#pragma unroll
        for (int ks = 0; ks < 2; ks++) {
            uint32_t ah[2][4];
            const int arow = lane & 15, acol = ks * 16 + (lane >> 4) * 8;
#pragma unroll
            for (int i = 0; i < 2; i++)
                ldsm_x4(ah[i], smem_u32(pA + (wm + i * 16 + arow) * 40 + acol));
            const int brow0 = wn + (lane & 7);
            const int bcol = ks * 16 + ((lane >> 3) & 1) * 8;
#pragma unroll
            for (int j = 0; j < 8; j++) {
                uint32_t bh[2], bl[2];
                ldsm_x2(bh, smem_u32(pBh + (brow0 + j * 8) * 40 + bcol));
                ldsm_x2(bl, smem_u32(pBl + (brow0 + j * 8) * 40 + bcol));
#pragma unroll
                for (int i = 0; i < 2; i++) {
                    mma_f16(acc[i][j], ah[i], bh);
                    mma_f16(acc[i][j], ah[i], bl);
                }
            }
        }
    }
    float* C; const float* bias; int ldc, cb, act = 0;
    if (MODE == 0) {
        int r = bn >> 7;
        if (r < 2)      { C = C0; bias = b0; ldc = 256; cb = bn; }
        else if (r < 6) { C = C1; bias = b1; ldc = 512; cb = bn - 256; }
        else            { C = C2; bias = b2; ldc = 256; cb = bn - 768; act = 1; }
    } else {
        C = C0; bias = b0; ldc = ldc0; cb = bn;
    }
#pragma unroll
    for (int i = 0; i < 2; i++) {
        int r0 = bm + wm + i * 16 + (lane >> 2);
#pragma unroll
        for (int j = 0; j < 8; j++) {
            int col = cb + wn + j * 8 + (lane & 3) * 2;
            float bb0 = bias[col], bb1 = bias[col + 1];
            float v0 = acc[i][j][0] + bb0, v1 = acc[i][j][1] + bb1;
            float v2 = acc[i][j][2] + bb0, v3 = acc[i][j][3] + bb1;
            if (MODE == 0 && act) {
                v0 = 0.5f * v0 * (1.0f + erff(v0 * 0.70710678118654752f));
                v1 = 0.5f * v1 * (1.0f + erff(v1 * 0.70710678118654752f));
                v2 = 0.5f * v2 * (1.0f + erff(v2 * 0.70710678118654752f));
                v3 = 0.5f * v3 * (1.0f + erff(v3 * 0.70710678118654752f));
            }
            float2 o01; o01.x = v0; o01.y = v1;
            float2 o23; o23.x = v2; o23.y = v3;
            *(float2*)(C + (size_t)r0 * ldc + col) = o01;
            *(float2*)(C + (size_t)(r0 + 8) * ldc + col) = o23;
        }
    }
}

// ---------------- merged q/kv postprocess ------------------------------------
__global__ void __launch_bounds__(256)
qkv_post(const float* __restrict__ temp, const float* __restrict__ qe) {
    int bid = blockIdx.x;
    int h = threadIdx.x >> 5, lane = threadIdx.x & 31;
    if (bid < BATCH * NTOK) {
        int bn = bid;
        int n = bn & (NTOK - 1);
        size_t off = (size_t)bn * CDIM + h * HD + lane;
        float v = g_q[off];
        float nrm = sqrtf(warp_sum(v * v));
        float qn = v / fmaxf(nrm, EPSF);
        int y = n >> 6, x = n & 63;
        int ch = min(y + 1, 63) - max(y - 1, 0) + 1;
        int cw = min(x + 1, 63) - max(x - 1, 0) + 1;
        float sls = logf((float)(ch * cw + PLP));
        float sp = log1pf(expf(temp[h]));
        float qsv = (qn + qe[h * HD + lane]) * sp * sls;
        g_q[off] = qn;
        __half qh = __float2half_rn(qsv);
        g_qsh[off] = qh;
        g_qsl[off] = __float2half_rn(qsv - __half2float(qh));
    } else {
        int bn = bid - BATCH * NTOK;
        size_t off = (size_t)bn * 2 * CDIM + h * HD + lane;
        float v = g_kv[off];
        float nrm = sqrtf(warp_sum(v * v));
        g_kv[off] = v / fmaxf(nrm, EPSF);
    }
}

// ---------------- pooled-kv postprocess: normalize k, fp16 splits ------------
__global__ void __launch_bounds__(256) kvpool_post() {
    int bp = blockIdx.x;
    int h = threadIdx.x >> 5, lane = threadIdx.x & 31;
    int c = h * HD + lane;
    size_t off = (size_t)bp * 2 * CDIM + c;
    float v = g_kvp[off];
    float nrm = sqrtf(warp_sum(v * v));
    float kn = v / fmaxf(nrm, EPSF);
    __half kh = __float2half_rn(kn);
    g_kph[(size_t)bp * CDIM + c] = kh;
    g_kpl[(size_t)bp * CDIM + c] = __float2half_rn(kn - __half2float(kh));
    g_vph[(size_t)bp * CDIM + c] = __float2half_rn(g_kvp[off + CDIM]);
}

// ---------------- 8x8 avg pool + LayerNorm (writes fp16) ---------------------
__global__ void __launch_bounds__(256)
pool_ln(const float* __restrict__ gw, const float* __restrict__ gb) {
    int bp = blockIdx.x;
    int b = bp >> 6, p = bp & 63;
    int py = p >> 3, px = p & 7;
    int c = threadIdx.x;
    const float* base = g_sr + (size_t)b * NTOK * CDIM;
    float s = 0.f;
    for (int iy = 0; iy < 8; iy++) {
        int y = py * 8 + iy;
        for (int ix = 0; ix < 8; ix++) {
            int n = y * RESHW + px * 8 + ix;
            s += base[(size_t)n * CDIM + c];
        }
    }
    float val = s * (1.0f / 64.0f);
    __shared__ float red[256];
    red[c] = val; __syncthreads();
    for (int st = 128; st > 0; st >>= 1) { if (c < st) red[c] += red[c + st]; __syncthreads(); }
    float mu = red[0] * (1.0f / 256.0f);
    __syncthreads();
    float dv = val - mu;
    red[c] = dv * dv; __syncthreads();
    for (int st = 128; st > 0; st >>= 1) { if (c < st) red[c] += red[c + st]; __syncthreads(); }
    float var = red[0] * (1.0f / 256.0f);
    float ov = dv * rsqrtf(var + 1e-5f) * gw[c] + gb[c];
    g_ph[(size_t)bp * CDIM + c] = __float2half_rn(ov);
}

// ---------------- cpb MLP ----------------------------------------------------
__global__ void __launch_bounds__(128)
cpb_kernel(const float* __restrict__ tbl, const float* __restrict__ w1,
           const float* __restrict__ b1, const float* __restrict__ w2,
           const float* __restrict__ b2) {
    int row = blockIdx.x;
    int tid = threadIdx.x;
    float t0 = tbl[row * 2 + 0], t1 = tbl[row * 2 + 1];
    float acc[8] = {};
    for (int j = tid; j < 512; j += 128) {
        float hv = fmaxf(t0 * w1[2 * j] + t1 * w1[2 * j + 1] + b1[j], 0.f);
#pragma unroll
        for (int o = 0; o < 8; o++) acc[o] += hv * w2[o * 512 + j];
    }
#pragma unroll
    for (int o = 0; o < 8; o++) acc[o] = warp_sum(acc[o]);
    __shared__ float sh[4][8];
    int wp = tid >> 5, lane = tid & 31;
    if (lane == 0)
#pragma unroll
        for (int o = 0; o < 8; o++) sh[wp][o] = acc[o];
    __syncthreads();
    if (tid < 8)
        g_cpb[(size_t)row * 8 + tid] =
            sh[0][tid] + sh[1][tid] + sh[2][tid] + sh[3][tid] + b2[tid];
}

// ================ K1: pool logits via mma (S = Qs @ Kp^T, 3-term) ============
__global__ void __launch_bounds__(256)
pool_logits() {
    __shared__ __align__(16) uint16_t sQh[128 * 40];
    __shared__ __align__(16) uint16_t sQl[128 * 40];
    __shared__ __align__(16) uint16_t sKh[64 * 40];
    __shared__ __align__(16) uint16_t sKl[64 * 40];
    const int mtile = blockIdx.x, bh = blockIdx.y;
    const int b = bh >> 3, h = bh & 7;
    const int tid = threadIdx.x, lane = tid & 31, wid = tid >> 5;
    const int wm = wid * 16;
    const int n0 = mtile * 128;
    for (int i = tid; i < 512; i += 256) {
        int row = i >> 2, part = i & 3;
        size_t src = ((size_t)(b * NTOK + n0 + row)) * CDIM + h * HD + part * 8;
        cp16(smem_u32(sQh + row * 40 + part * 8), g_qsh + src);
        cp16(smem_u32(sQl + row * 40 + part * 8), g_qsl + src);
    }
    {
        int i = tid;
        if (i < 256) {
            int row = i >> 2, part = i & 3;
            size_t src = ((size_t)(b * PLP + row)) * CDIM + h * HD + part * 8;
            cp16(smem_u32(sKh + row * 40 + part * 8), g_kph + src);
            cp16(smem_u32(sKl + row * 40 + part * 8), g_kpl + src);
        }
    }
    CP_COMMIT(); CP_WAIT0();
    __syncthreads();
    float acc[8][4] = {};
#pragma unroll
    for (int ks = 0; ks < 2; ks++) {
        uint32_t qh[4], ql[4];
        const int arow = lane & 15, acol = ks * 16 + (lane >> 4) * 8;
        ldsm_x4(qh, smem_u32(sQh + (wm + arow) * 40 + acol));
        ldsm_x4(ql, smem_u32(sQl + (wm + arow) * 40 + acol));
        const int brow0 = lane & 7;
        const int bcol = ks * 16 + ((lane >> 3) & 1) * 8;
#pragma unroll
        for (int j = 0; j < 8; j++) {
            uint32_t kh[2], kl[2];
            ldsm_x2(kh, smem_u32(sKh + (brow0 + j * 8) * 40 + bcol));
            ldsm_x2(kl, smem_u32(sKl + (brow0 + j * 8) * 40 + bcol));
            mma_f16(acc[j], qh, kh);
            mma_f16(acc[j], ql, kh);
            mma_f16(acc[j], qh, kl);
        }
    }
    int r0 = n0 + wm + (lane >> 2);
#pragma unroll
    for (int j = 0; j < 8; j++) {
        int col = j * 8 + (lane & 3) * 2;
        float2 a; a.x = acc[j][0]; a.y = acc[j][1];
        float2 c; c.x = acc[j][2]; c.y = acc[j][3];
        *(float2*)(g_spool + ((size_t)bh * NTOK + r0) * PLP + col) = a;
        *(float2*)(g_spool + ((size_t)bh * NTOK + r0 + 8) * PLP + col) = c;
    }
}

// ================ K2: local logits + softmax + local AV ======================
#define AKW 0
#define AVW 3366
#define AQS 6732
#define AQN 7788
#define ALG 8844
#define ALT 11532
#define ASMEMB ((11532 + 9 * 33 + 3) * 4)

__global__ void __launch_bounds__(1024)
attn_soft(const float* __restrict__ rpb, const float* __restrict__ lt,
          const float* __restrict__ lb, const int* __restrict__ rel_idx) {
    extern __shared__ float sh[];
    float* Kw  = sh + AKW;     // [102][33]
    float* Vw  = sh + AVW;
    float* qss = sh + AQS;     // [32][33]
    float* qns = sh + AQN;
    float* lg  = sh + ALG;     // [32][84]
    float* lts = sh + ALT;     // [9][33]
    int blk = blockIdx.x;
    int ntile = blk & 127;
    int hh = (blk >> 7) & 7;
    int b = blk >> 10;
    int bh = b * 8 + hh;
    int tid = threadIdx.x, w = tid >> 5, lane = tid & 31;
    int y = ntile >> 1, x0 = (ntile & 1) << 5;

    for (int i = tid; i < 3264; i += 1024) {
        int vec = i >> 5, d = i & 31;
        int r = vec / 34, c = vec - r * 34;
        int yy = y + r - 1, xx = x0 - 1 + c;
        float kv0 = 0.f, vv0 = 0.f;
        if ((unsigned)yy < 64u && (unsigned)xx < 64u) {
            size_t base = ((size_t)(b * NTOK + yy * 64 + xx)) * 512 + hh * 32 + d;
            kv0 = g_kv[base];
            vv0 = g_kv[base + 256];
        }
        Kw[vec * 33 + d] = kv0;
        Vw[vec * 33 + d] = vv0;
    }
    if (tid < 288) {
        int d = tid / 9, l = tid - d * 9;
        lts[l * 33 + d] = lt[hh * 288 + tid];
    }
    int n = ntile * 32 + w;
    size_t qoff = ((size_t)(b * NTOK + n)) * 256 + hh * 32 + lane;
    qss[w * 33 + lane] = __half2float(g_qsh[qoff]) + __half2float(g_qsl[qoff]);
    qns[w * 33 + lane] = g_q[qoff];
    __syncthreads();

    int xl = n & 31;
    const int* rix = rel_idx + (size_t)n * 64;
    // 18 outputs: 0..8 local logits, 9..17 learnable corrections
    {
        int o = lane;
        if (o < 18) {
            const float* kr;
            const float* qr;
            float bias;
            int slot;
            if (o < 9) {
                int r = o / 3, dc = o - r * 3;
                kr = Kw + (r * 34 + xl + dc) * 33;
                qr = qss + w * 33;
                bias = rpb[hh * 9 + o];
                slot = 64 + o;
            } else {
                int l = o - 9;
                kr = lts + l * 33;
                qr = qns + w * 33;
                bias = lb[hh * 9 + l];
                slot = 73 + l;
            }
            float acc = bias;
#pragma unroll
            for (int d = 0; d < 32; d++) acc += qr[d] * kr[d];
            lg[w * 84 + slot] = acc;
        }
    }
    __syncwarp();
    size_t soff = ((size_t)bh * NTOK + n) * 64;
    float s0 = g_spool[soff + lane] + g_cpb[(size_t)rix[lane] * 8 + hh];
    float s1 = g_spool[soff + 32 + lane] + g_cpb[(size_t)rix[lane + 32] * 8 + hh];
    float l0 = (lane < 9) ? lg[w * 84 + 64 + lane] : -3.4e38f;
    float mx = warp_max(fmaxf(fmaxf(s0, s1), l0));
    float e0 = expf(s0 - mx), e1 = expf(s1 - mx);
    float e2 = (lane < 9) ? expf(l0 - mx) : 0.f;
    float inv = 1.0f / warp_sum(e0 + e1 + e2);
    float p0 = e0 * inv, p1 = e1 * inv;
    __half p0h = __float2half_rn(p0);
    __half p1h = __float2half_rn(p1);
    g_ph2[soff + lane] = p0h;
    g_pl2[soff + lane] = __float2half_rn(p0 - __half2float(p0h));
    g_ph2[soff + 32 + lane] = p1h;
    g_pl2[soff + 32 + lane] = __float2half_rn(p1 - __half2float(p1h));
    if (lane < 9) lg[w * 84 + lane] = e2 * inv + lg[w * 84 + 73 + lane];
    __syncwarp();
    float outv = 0.f;
#pragma unroll
    for (int l = 0; l < 9; l++) {
        int r = l / 3, dc = l - r * 3;
        outv += lg[w * 84 + l] * Vw[(r * 34 + xl + dc) * 33 + lane];
    }
    g_lout[(size_t)bh * (NTOK * HD) + (size_t)n * HD + lane] = outv;
}

// ================ K3: pool AV via mma (X = P @ Vp), add local, gate ==========
__global__ void __launch_bounds__(256)
pool_av() {
    __shared__ __align__(16) uint16_t sPh[128 * 72];
    __shared__ __align__(16) uint16_t sPl[128 * 72];
    __shared__ __align__(16) uint16_t sVt[32 * 72];
    const int mtile = blockIdx.x, bh = blockIdx.y;
    const int b = bh >> 3, h = bh & 7;
    const int tid = threadIdx.x, lane = tid & 31, wid = tid >> 5;
    const int wm = wid * 16;
    const int n0 = mtile * 128;
    for (int i = tid; i < 1024; i += 256) {
        int row = i >> 3, part = i & 7;
        size_t src = ((size_t)bh * NTOK + n0 + row) * 64 + part * 8;
        cp16(smem_u32(sPh + row * 72 + part * 8), g_ph2 + src);
        cp16(smem_u32(sPl + row * 72 + part * 8), g_pl2 + src);
    }
    CP_COMMIT();
    for (int i = tid; i < 2048; i += 256) {
        int p = i >> 5, d = i & 31;
        sVt[d * 72 + p] =
            *(const uint16_t*)&g_vph[((size_t)(b * PLP + p)) * CDIM + h * HD + d];
    }
    CP_WAIT0();
    __syncthreads();
    float acc[4][4] = {};
#pragma unroll
    for (int kc = 0; kc < 4; kc++) {
        uint32_t ph[4], pl[4];
        const int arow = lane & 15, acol = kc * 16 + (lane >> 4) * 8;
        ldsm_x4(ph, smem_u32(sPh + (wm + arow) * 72 + acol));
        ldsm_x4(pl, smem_u32(sPl + (wm + arow) * 72 + acol));
        const int brow0 = lane & 7;
        const int bcol = kc * 16 + ((lane >> 3) & 1) * 8;
#pragma unroll
        for (int j = 0; j < 4; j++) {
            uint32_t bv[2];
            ldsm_x2(bv, smem_u32(sVt + (brow0 + j * 8) * 72 + bcol));
            mma_f16(acc[j], ph, bv);
            mma_f16(acc[j], pl, bv);
        }
    }
    int r0 = n0 + wm + (lane >> 2);
#pragma unroll
    for (int j = 0; j < 4; j++) {
        int d = j * 8 + (lane & 3) * 2;
#pragma unroll
        for (int hf = 0; hf < 2; hf++) {
            int n = r0 + hf * 8;
            float2 lo = *(const float2*)(g_lout + (size_t)bh * (NTOK * HD) +
                                         (size_t)n * HD + d);
            float gt = g_gate[((size_t)(b * NTOK + n)) * 8 + h];
            float o0 = (acc[j][hf * 2 + 0] + lo.x) * gt;
            float o1 = (acc[j][hf * 2 + 1] + lo.y) * gt;
            *(__half2*)(g_ah + ((size_t)(b * NTOK + n)) * CDIM + h * HD + d) =
                __floats2half2_rn(o0, o1);
        }
    }
}

// ---------------- launch ----------------------------------------------------
extern "C" void kernel_launch(void* const* d_in, const int* in_sizes, int n_in,
                              void* d_out, int out_size) {
    const float* x      = (const float*)d_in[0];
    const float* rct    = (const float*)d_in[1];
    const float* q_w    = (const float*)d_in[2];
    const float* q_b    = (const float*)d_in[3];
    const float* kv_w   = (const float*)d_in[4];
    const float* kv_b   = (const float*)d_in[5];
    const float* temp   = (const float*)d_in[6];
    const float* qe     = (const float*)d_in[7];
    const float* rpb    = (const float*)d_in[8];
    const float* lt     = (const float*)d_in[9];
    const float* lb     = (const float*)d_in[10];
    const float* cpb1_w = (const float*)d_in[11];
    const float* cpb1_b = (const float*)d_in[12];
    const float* cpb2_w = (const float*)d_in[13];
    const float* cpb2_b = (const float*)d_in[14];
    const float* sr_w   = (const float*)d_in[15];
    const float* sr_b   = (const float*)d_in[16];
    const float* norm_g = (const float*)d_in[17];
    const float* norm_b = (const float*)d_in[18];
    const float* wg_w   = (const float*)d_in[19];
    const float* wg0_w  = (const float*)d_in[20];
    const float* wg1_w  = (const float*)d_in[21];
    const float* proj_w = (const float*)d_in[22];
    const float* proj_b = (const float*)d_in[23];
    const int*   ridx   = (const int*)d_in[24];
    float* out = (float*)d_out;

    float *pq, *pkv, *psr, *pkvp;
    __half *pxh, *pwh, *pwl, *pph, *pah;
    cudaGetSymbolAddress((void**)&pq,   g_q);
    cudaGetSymbolAddress((void**)&pkv,  g_kv);
    cudaGetSymbolAddress((void**)&psr,  g_sr);
    cudaGetSymbolAddress((void**)&pkvp, g_kvp);
    cudaGetSymbolAddress((void**)&pxh,  g_xh);
    cudaGetSymbolAddress((void**)&pwh,  g_wh);
    cudaGetSymbolAddress((void**)&pwl,  g_wl);
    cudaGetSymbolAddress((void**)&pph,  g_ph);
    cudaGetSymbolAddress((void**)&pah,  g_ah);

    cudaFuncSetAttribute(gemm_f16<0>,
                         cudaFuncAttributeMaxDynamicSharedMemorySize, GSMEM);
    cudaFuncSetAttribute(gemm_f16<1>,
                         cudaFuncAttributeMaxDynamicSharedMemorySize, GSMEM);
    cudaFuncSetAttribute(attn_soft,
                         cudaFuncAttributeMaxDynamicSharedMemorySize, ASMEMB);

    const int M = BATCH * NTOK;                       // 16384

    conv_x_gate<<<M / 8, 256>>>(x, wg_w, wg0_w, wg1_w);             // 0
    conv_w<<<320, 256>>>(q_w, kv_w, sr_w, proj_w);                  // 1
    cpb_kernel<<<TBLN, 128>>>(rct, cpb1_w, cpb1_b, cpb2_w, cpb2_b); // 2
    dim3 gf(8, M / 128);
    gemm_f16<0><<<gf, 256, GSMEM>>>(pxh, pwh, pwl,                  // 3 (profiled)
                                    pq, pkv, psr, q_b, kv_b, sr_b, 0);
    qkv_post<<<2 * M, 256>>>(temp, qe);                             // 4
    pool_ln<<<BATCH * PLP, 256>>>(norm_g, norm_b);                  // 5
    dim3 gp(4, 2);
    gemm_f16<1><<<gp, 256, GSMEM>>>(pph, pwh + 256 * 256, pwl + 256 * 256,
                                    pkvp, nullptr, nullptr, kv_b, nullptr,
                                    nullptr, 512);                  // 6
    kvpool_post<<<BATCH * PLP, 256>>>();                            // 7
    dim3 ga(NTOK / 128, BH);
    pool_logits<<<ga, 256>>>();                                     // 8
    attn_soft<<<BATCH * NH * (NTOK / 32), 1024, ASMEMB>>>(rpb, lt, lb, ridx); // 9
    pool_av<<<ga, 256>>>();                                         // 10
    dim3 gj(2, M / 128);
    gemm_f16<1><<<gj, 256, GSMEM>>>(pah, pwh + 1024 * 256, pwl + 1024 * 256,
                                    out, nullptr, nullptr, proj_b, nullptr,
                                    nullptr, 256);                  // 11
}

// round 9
// speedup vs baseline: 1.5851x; 1.0876x over previous
#include <cuda_runtime.h>
#include <cuda_bf16.h>
#include <cuda_fp16.h>
#include <math.h>
#include <stdint.h>

#define BATCH 4
#define NTOK  4096      // N = 64*64
#define CDIM  256
#define NH    8
#define HD    32
#define RESHW 64
#define PLP   64        // pooled length (8*8)
#define TBLN  4096
#define BH    (BATCH*NH)
#define EPSF  1.1920929e-07f

// ---------------- scratch (device globals; no dynamic alloc) ----------------
__device__ float g_q   [BATCH*NTOK*CDIM];        // q_norm fp32
__device__ float g_kv  [BATCH*NTOK*2*CDIM];      // kv; k half normalized
__device__ float g_sr  [BATCH*NTOK*CDIM];
__device__ float g_gate[BATCH*NTOK*NH];
__device__ float g_kvp [BATCH*PLP*2*CDIM];
__device__ float g_cpb [TBLN*NH];
__device__ __half g_xh [BATCH*NTOK*CDIM];        // x fp16
__device__ __half g_wh [1280*CDIM];              // weights hi
__device__ __half g_wl [1280*CDIM];              // weights lo
__device__ __half g_ph [BATCH*PLP*CDIM];         // pooled+LN fp16
__device__ __half g_ah [BATCH*NTOK*CDIM];        // attention out fp16
__device__ __half g_qsh[BATCH*NTOK*CDIM];        // q_scaled hi
__device__ __half g_qsl[BATCH*NTOK*CDIM];        // q_scaled lo
__device__ __half g_kph[BATCH*PLP*CDIM];         // k_pool norm hi
__device__ __half g_kpl[BATCH*PLP*CDIM];         // k_pool norm lo
__device__ __half g_vph[BATCH*PLP*CDIM];         // v_pool fp16
__device__ float  g_spool[BH*NTOK*PLP];          // pool logits
__device__ __half g_ph2[BH*NTOK*PLP];            // pool probs hi
__device__ __half g_pl2[BH*NTOK*PLP];            // pool probs lo
__device__ float  g_lout[BH*NTOK*HD];            // local partial out

__device__ __forceinline__ float warp_sum(float v) {
#pragma unroll
    for (int o = 16; o; o >>= 1) v += __shfl_xor_sync(0xffffffffu, v, o);
    return v;
}
__device__ __forceinline__ float warp_max(float v) {
#pragma unroll
    for (int o = 16; o; o >>= 1) v = fmaxf(v, __shfl_xor_sync(0xffffffffu, v, o));
    return v;
}

// ================= helpers ==================================================
__device__ __forceinline__ uint32_t smem_u32(const void* p) {
    uint32_t a;
    asm("{ .reg .u64 t; cvta.to.shared.u64 t, %1; cvt.u32.u64 %0, t; }"
        : "=r"(a) : "l"(p));
    return a;
}
__device__ __forceinline__ void ldsm_x4(uint32_t* r, uint32_t addr) {
    asm volatile("ldmatrix.sync.aligned.m8n8.x4.shared.b16 {%0,%1,%2,%3}, [%4];"
                 : "=r"(r[0]), "=r"(r[1]), "=r"(r[2]), "=r"(r[3]) : "r"(addr));
}
__device__ __forceinline__ void ldsm_x2(uint32_t* r, uint32_t addr) {
    asm volatile("ldmatrix.sync.aligned.m8n8.x2.shared.b16 {%0,%1}, [%2];"
                 : "=r"(r[0]), "=r"(r[1]) : "r"(addr));
}
__device__ __forceinline__ void mma_f16(float* c, const uint32_t* a,
                                        const uint32_t* b) {
    asm volatile(
        "mma.sync.aligned.m16n8k16.row.col.f32.f16.f16.f32 "
        "{%0,%1,%2,%3}, {%4,%5,%6,%7}, {%8,%9}, {%0,%1,%2,%3};"
        : "+f"(c[0]), "+f"(c[1]), "+f"(c[2]), "+f"(c[3])
        : "r"(a[0]), "r"(a[1]), "r"(a[2]), "r"(a[3]), "r"(b[0]), "r"(b[1]));
}
__device__ __forceinline__ void cp16(uint32_t dst, const void* src) {
    asm volatile("cp.async.cg.shared.global [%0], [%1], 16;"
                 :: "r"(dst), "l"(src));
}
#define CP_COMMIT() asm volatile("cp.async.commit_group;" ::: "memory")
#define CP_WAIT0()  asm volatile("cp.async.wait_group 0;" ::: "memory")

// ---------------- x convert (fp16) + gating (single x read) ------------------
__global__ void __launch_bounds__(256)
conv_x_gate(const float* __restrict__ x, const float* __restrict__ wg,
            const float* __restrict__ wg0, const float* __restrict__ wg1) {
    int t = blockIdx.x * 8 + (threadIdx.x >> 5);
    int lane = threadIdx.x & 31;
    const float* xt = x + (size_t)t * CDIM;
    float4 xa = *(const float4*)(xt + lane * 8);
    float4 xb = *(const float4*)(xt + lane * 8 + 4);
    __half2 h0 = __floats2half2_rn(xa.x, xa.y);
    __half2 h1 = __floats2half2_rn(xa.z, xa.w);
    __half2 h2 = __floats2half2_rn(xb.x, xb.y);
    __half2 h3 = __floats2half2_rn(xb.z, xb.w);
    uint4 u;
    u.x = *(uint32_t*)&h0; u.y = *(uint32_t*)&h1;
    u.z = *(uint32_t*)&h2; u.w = *(uint32_t*)&h3;
    *(uint4*)(g_xh + (size_t)t * CDIM + lane * 8) = u;
    float d[10];
#pragma unroll
    for (int i = 0; i < 10; i++) {
        const float* wr = (i < 4) ? wg + i * CDIM
                        : (i < 8) ? wg1 + (i - 4) * CDIM
                                  : wg0 + (i - 8) * CDIM;
        float4 wa = *(const float4*)(wr + lane * 8);
        float4 wb = *(const float4*)(wr + lane * 8 + 4);
        float s = xa.x * wa.x + xa.y * wa.y + xa.z * wa.z + xa.w * wa.w
                + xb.x * wb.x + xb.y * wb.y + xb.z * wb.z + xb.w * wb.w;
        d[i] = warp_sum(s);
    }
    float m0 = fmaxf(fmaxf(d[0], d[1]), fmaxf(d[2], d[3]));
    float e[4], se = 0.f;
#pragma unroll
    for (int i = 0; i < 4; i++) { e[i] = expf(d[i] - m0); se += e[i]; }
    float gsm[4];
#pragma unroll
    for (int i = 0; i < 4; i++) gsm[i] = e[i] / se;
    int i1 = 0;
#pragma unroll
    for (int i = 1; i < 4; i++) if (gsm[i] > gsm[i1]) i1 = i;
    int i2 = -1;
#pragma unroll
    for (int i = 0; i < 4; i++) {
        if (i == i1) continue;
        if (i2 < 0 || gsm[i] > gsm[i2]) i2 = i;
    }
    float rs = fmaxf(gsm[i1] + gsm[i2], EPSF);
    float routed[4];
#pragma unroll
    for (int i = 0; i < 4; i++)
        routed[i] = (i == i1 || i == i2) ? gsm[i] / rs * 2.f : 0.f;
    float m1 = fmaxf(fmaxf(d[4], d[5]), fmaxf(d[6], d[7]));
    float es[4], ss = 0.f;
#pragma unroll
    for (int i = 0; i < 4; i++) { es[i] = expf(d[4 + i] - m1); ss += es[i]; }
    float shg[4];
#pragma unroll
    for (int i = 0; i < 4; i++) shg[i] = es[i] / ss * 4.f;
    float m2 = fmaxf(d[8], d[9]);
    float e8 = expf(d[8] - m2), e9 = expf(d[9] - m2);
    float w00 = e8 / (e8 + e9) * 2.f;
    float w01 = e9 / (e8 + e9) * 2.f;
    if (lane < NH) {
        float v = (lane < 4) ? w00 * shg[lane] : w01 * routed[lane - 4];
        g_gate[(size_t)t * NH + lane] = v;
    }
}

// ---------------- all-weights fp16 hi/lo convert -----------------------------
__global__ void __launch_bounds__(256)
conv_w(const float* __restrict__ qw, const float* __restrict__ kvw,
       const float* __restrict__ srw, const float* __restrict__ pjw) {
    int i = blockIdx.x * 256 + threadIdx.x;   // float4 index, 81920 total
    int row = i >> 6;
    const float4* src;
    int off;
    if (row < 256)       { src = (const float4*)qw;  off = i; }
    else if (row < 768)  { src = (const float4*)kvw; off = i - 256 * 64; }
    else if (row < 1024) { src = (const float4*)srw; off = i - 768 * 64; }
    else                 { src = (const float4*)pjw; off = i - 1024 * 64; }
    float4 v = src[off];
    __half a0 = __float2half_rn(v.x), a1 = __float2half_rn(v.y);
    __half a2 = __float2half_rn(v.z), a3 = __float2half_rn(v.w);
    __half b0 = __float2half_rn(v.x - __half2float(a0));
    __half b1 = __float2half_rn(v.y - __half2float(a1));
    __half b2 = __float2half_rn(v.z - __half2float(a2));
    __half b3 = __float2half_rn(v.w - __half2float(a3));
    ushort4 H, L;
    H.x = *(uint16_t*)&a0; H.y = *(uint16_t*)&a1;
    H.z = *(uint16_t*)&a2; H.w = *(uint16_t*)&a3;
    L.x = *(uint16_t*)&b0; L.y = *(uint16_t*)&b1;
    L.z = *(uint16_t*)&b2; L.w = *(uint16_t*)&b3;
    ((ushort4*)g_wh)[i] = H;
    ((ushort4*)g_wl)[i] = L;
}

// ================= double-buffered 2-term fp16 GEMM =========================
// MODE 0: fused q/kv/sr with fused q/k per-head L2 normalization epilogue.
// MODE 1: plain single output.
#define MATSZ (128 * 40)
#define GSMEM (2 * 3 * MATSZ * 2)   // 61440 B

template<int MODE>
__global__ void __launch_bounds__(256, 2)
gemm_f16(const __half* __restrict__ A,
         const __half* __restrict__ Wh, const __half* __restrict__ Wl,
         float* __restrict__ C0, float* __restrict__ C1, float* __restrict__ C2,
         const float* __restrict__ b0, const float* __restrict__ b1,
         const float* __restrict__ b2, int ldc0,
         const float* __restrict__ temp, const float* __restrict__ qe) {
    extern __shared__ uint16_t sd[];
    const int bm = blockIdx.y * 128, bn = blockIdx.x * 128;
    const int tid = threadIdx.x, lane = tid & 31, wid = tid >> 5;
    const int wm = (wid & 3) * 32, wn = (wid >> 2) * 64;
    float acc[2][8][4] = {};

    const __half* gsrc[3] = {
        A + (size_t)bm * 256, Wh + (size_t)bn * 256, Wl + (size_t)bn * 256};

    // hoisted ldmatrix base addresses (stage 0, ks 0)
    const uint32_t sb0 = smem_u32(sd);
    uint32_t aAdr[2];
#pragma unroll
    for (int i = 0; i < 2; i++)
        aAdr[i] = sb0 + 2 * ((wm + i * 16 + (lane & 15)) * 40 + (lane >> 4) * 8);
    uint32_t bAdr[4];
    {
        int m = lane >> 3;
#pragma unroll
        for (int jp = 0; jp < 4; jp++)
            bAdr[jp] = sb0 + 2 * (MATSZ + (wn + jp * 16 + (m >> 1) * 8 +
                                           (lane & 7)) * 40 + (m & 1) * 8);
    }

#pragma unroll
    for (int m = 0; m < 3; m++)
#pragma unroll
        for (int s = 0; s < 2; s++) {
            int seg = tid + s * 256;
            int row = seg >> 2, part = seg & 3;
            cp16(smem_u32(sd + m * MATSZ + row * 40 + part * 8),
                 gsrc[m] + (size_t)row * 256 + part * 8);
        }
    CP_COMMIT();

    for (int kc = 0; kc < 8; kc++) {
        const int stg = kc & 1;
        const uint32_t so = (uint32_t)stg * (3 * MATSZ * 2);
        CP_WAIT0();
        __syncthreads();
        if (kc < 7) {
            const int nb = (stg ^ 1) * 3 * MATSZ;
            const int ko = (kc + 1) * 32;
#pragma unroll
            for (int m = 0; m < 3; m++)
#pragma unroll
                for (int s = 0; s < 2; s++) {
                    int seg = tid + s * 256;
                    int row = seg >> 2, part = seg & 3;
                    cp16(smem_u32(sd + nb + m * MATSZ + row * 40 + part * 8),
                         gsrc[m] + (size_t)row * 256 + ko + part * 8);
                }
            CP_COMMIT();
        }
#pragma unroll
        for (int ks = 0; ks < 2; ks++) {
            const uint32_t so2 = so + ks * 32;
            uint32_t ah[2][4];
            ldsm_x4(ah[0], aAdr[0] + so2);
            ldsm_x4(ah[1], aAdr[1] + so2);
#pragma unroll
            for (int jp = 0; jp < 4; jp++) {
                uint32_t bh[4], bl[4];
                ldsm_x4(bh, bAdr[jp] + so2);
                ldsm_x4(bl, bAdr[jp] + so2 + 2 * MATSZ);
#pragma unroll
                for (int i = 0; i < 2; i++) {
                    mma_f16(acc[i][jp * 2], ah[i], bh);
                    mma_f16(acc[i][jp * 2], ah[i], bl);
                    mma_f16(acc[i][jp * 2 + 1], ah[i], bh + 2);
                    mma_f16(acc[i][jp * 2 + 1], ah[i], bl + 2);
                }
            }
        }
    }

    if (MODE == 0) {
        const int r = bn >> 7;
        const bool isQ = r < 2, isK = (r == 2 || r == 3), isSR = r >= 6;
        const float* bias = isQ ? b0 : (r < 6 ? b1 : b2);
        const int cb = isQ ? bn : (r < 6 ? bn - 256 : bn - 768);
        // add bias (+GELU for sr) into regs
#pragma unroll
        for (int i = 0; i < 2; i++)
#pragma unroll
            for (int j = 0; j < 8; j++) {
                int col = cb + wn + j * 8 + (lane & 3) * 2;
                float bb0 = bias[col], bb1 = bias[col + 1];
                acc[i][j][0] += bb0; acc[i][j][1] += bb1;
                acc[i][j][2] += bb0; acc[i][j][3] += bb1;
                if (isSR) {
#pragma unroll
                    for (int t = 0; t < 4; t++) {
                        float v = acc[i][j][t];
                        acc[i][j][t] =
                            0.5f * v * (1.0f + erff(v * 0.70710678118654752f));
                    }
                }
            }
        if (isQ || isK) {
            // per-(row, head) sum of squares via smem atomics (sd stage0 idle)
            float* sums = (float*)sd;
            sums[tid] = 0.f; sums[tid + 256] = 0.f;
            __syncthreads();
#pragma unroll
            for (int i = 0; i < 2; i++)
#pragma unroll
                for (int half = 0; half < 2; half++)
#pragma unroll
                    for (int hg = 0; hg < 2; hg++) {
                        float p = 0.f;
#pragma unroll
                        for (int j = hg * 4; j < hg * 4 + 4; j++)
                            p += acc[i][j][half * 2] * acc[i][j][half * 2] +
                                 acc[i][j][half * 2 + 1] * acc[i][j][half * 2 + 1];
                        p += __shfl_xor_sync(0xffffffffu, p, 1);
                        p += __shfl_xor_sync(0xffffffffu, p, 2);
                        if ((lane & 3) == 0) {
                            int rr = wm + i * 16 + (lane >> 2) + half * 8;
                            atomicAdd(&sums[rr * 4 + (wn >> 5) + hg], p);
                        }
                    }
            __syncthreads();
            if (isQ) {
                float sp[2];
#pragma unroll
                for (int hg = 0; hg < 2; hg++)
                    sp[hg] = log1pf(expf(temp[((bn + wn) >> 5) + hg]));
                float sls[2][2];
#pragma unroll
                for (int i = 0; i < 2; i++)
#pragma unroll
                    for (int half = 0; half < 2; half++) {
                        int row = wm + i * 16 + (lane >> 2) + half * 8;
                        int n = (bm + row) & (NTOK - 1);
                        int yq = n >> 6, xq = n & 63;
                        int chh = min(yq + 1, 63) - max(yq - 1, 0) + 1;
                        int cww = min(xq + 1, 63) - max(xq - 1, 0) + 1;
                        sls[i][half] = logf((float)(chh * cww + PLP));
                    }
#pragma unroll
                for (int i = 0; i < 2; i++)
#pragma unroll
                    for (int j = 0; j < 8; j++) {
                        int hg = j >> 2;
                        int gcol = bn + wn + j * 8 + (lane & 3) * 2;
                        float qe0 = qe[gcol];       // qe is [8][32] = 256 linear
                        float qe1 = qe[gcol + 1];
#pragma unroll
                        for (int half = 0; half < 2; half++) {
                            int row = wm + i * 16 + (lane >> 2) + half * 8;
                            float inv = 1.f /
                                fmaxf(sqrtf(sums[row * 4 + (wn >> 5) + hg]), EPSF);
                            float q0 = acc[i][j][half * 2] * inv;
                            float q1 = acc[i][j][half * 2 + 1] * inv;
                            size_t go = (size_t)(bm + row) * 256 + gcol;
                            float2 f2; f2.x = q0; f2.y = q1;
                            *(float2*)(g_q + go) = f2;
                            float m = sp[hg] * sls[i][half];
                            float s0 = (q0 + qe0) * m, s1 = (q1 + qe1) * m;
                            __half hh0 = __float2half_rn(s0);
                            __half hh1 = __float2half_rn(s1);
                            *(__half2*)(g_qsh + go) = __halves2half2(hh0, hh1);
                            *(__half2*)(g_qsl + go) = __halves2half2(
                                __float2half_rn(s0 - __half2float(hh0)),
                                __float2half_rn(s1 - __half2float(hh1)));
                        }
                    }
            } else {  // isK: normalize, write fp32 g_kv (k half)
#pragma unroll
                for (int i = 0; i < 2; i++)
#pragma unroll
                    for (int j = 0; j < 8; j++) {
                        int hg = j >> 2;
                        int gcol = cb + wn + j * 8 + (lane & 3) * 2;
#pragma unroll
                        for (int half = 0; half < 2; half++) {
                            int row = wm + i * 16 + (lane >> 2) + half * 8;
                            float inv = 1.f /
                                fmaxf(sqrtf(sums[row * 4 + (wn >> 5) + hg]), EPSF);
                            float2 f2;
                            f2.x = acc[i][j][half * 2] * inv;
                            f2.y = acc[i][j][half * 2 + 1] * inv;
                            *(float2*)(g_kv + (size_t)(bm + row) * 512 + gcol) = f2;
                        }
                    }
            }
        } else {  // v tiles / sr: plain store
            float* C = isSR ? C2 : C1;
            int ldc = isSR ? 256 : 512;
#pragma unroll
            for (int i = 0; i < 2; i++) {
                int r0 = bm + wm + i * 16 + (lane >> 2);
#pragma unroll
                for (int j = 0; j < 8; j++) {
                    int col = cb + wn + j * 8 + (lane & 3) * 2;
                    float2 o01; o01.x = acc[i][j][0]; o01.y = acc[i][j][1];
                    float2 o23; o23.x = acc[i][j][2]; o23.y = acc[i][j][3];
                    *(float2*)(C + (size_t)r0 * ldc + col) = o01;
                    *(float2*)(C + (size_t)(r0 + 8) * ldc + col) = o23;
                }
            }
        }
        return;
    }
    // MODE 1 epilogue
#pragma unroll
    for (int i = 0; i < 2; i++) {
        int r0 = bm + wm + i * 16 + (lane >> 2);
#pragma unroll
        for (int j = 0; j < 8; j++) {
            int col = bn + wn + j * 8 + (lane & 3) * 2;
            float bb0 = b0[col], bb1 = b0[col + 1];
            float2 o01; o01.x = acc[i][j][0] + bb0; o01.y = acc[i][j][1] + bb1;
            float2 o23; o23.x = acc[i][j][2] + bb0; o23.y = acc[i][j][3] + bb1;
            *(float2*)(C0 + (size_t)r0 * ldc0 + col) = o01;
            *(float2*)(C0 + (size_t)(r0 + 8) * ldc0 + col) = o23;
        }
    }
}

// ---------------- pooled-kv postprocess: normalize k, fp16 splits ------------
__global__ void __launch_bounds__(256) kvpool_post() {
    int bp = blockIdx.x;
    int h = threadIdx.x >> 5, lane = threadIdx.x & 31;
    int c = h * HD + lane;
    size_t off = (size_t)bp * 2 * CDIM + c;
    float v = g_kvp[off];
    float nrm = sqrtf(warp_sum(v * v));
    float kn = v / fmaxf(nrm, EPSF);
    __half kh = __float2half_rn(kn);
    g_kph[(size_t)bp * CDIM + c] = kh;
    g_kpl[(size_t)bp * CDIM + c] = __float2half_rn(kn - __half2float(kh));
    g_vph[(size_t)bp * CDIM + c] = __float2half_rn(g_kvp[off + CDIM]);
}

// ---------------- 8x8 avg pool + LayerNorm (writes fp16) ---------------------
__global__ void __launch_bounds__(256)
pool_ln(const float* __restrict__ gw, const float* __restrict__ gb) {
    int bp = blockIdx.x;
    int b = bp >> 6, p = bp & 63;
    int py = p >> 3, px = p & 7;
    int c = threadIdx.x;
    const float* base = g_sr + (size_t)b * NTOK * CDIM;
    float s = 0.f;
    for (int iy = 0; iy < 8; iy++) {
        int y = py * 8 + iy;
        for (int ix = 0; ix < 8; ix++) {
            int n = y * RESHW + px * 8 + ix;
            s += base[(size_t)n * CDIM + c];
        }
    }
    float val = s * (1.0f / 64.0f);
    __shared__ float red[256];
    red[c] = val; __syncthreads();
    for (int st = 128; st > 0; st >>= 1) { if (c < st) red[c] += red[c + st]; __syncthreads(); }
    float mu = red[0] * (1.0f / 256.0f);
    __syncthreads();
    float dv = val - mu;
    red[c] = dv * dv; __syncthreads();
    for (int st = 128; st > 0; st >>= 1) { if (c < st) red[c] += red[c + st]; __syncthreads(); }
    float var = red[0] * (1.0f / 256.0f);
    float ov = dv * rsqrtf(var + 1e-5f) * gw[c] + gb[c];
    g_ph[(size_t)bp * CDIM + c] = __float2half_rn(ov);
}

// ---------------- cpb MLP ----------------------------------------------------
__global__ void __launch_bounds__(128)
cpb_kernel(const float* __restrict__ tbl, const float* __restrict__ w1,
           const float* __restrict__ b1, const float* __restrict__ w2,
           const float* __restrict__ b2) {
    int row = blockIdx.x;
    int tid = threadIdx.x;
    float t0 = tbl[row * 2 + 0], t1 = tbl[row * 2 + 1];
    float acc[8] = {};
    for (int j = tid; j < 512; j += 128) {
        float hv = fmaxf(t0 * w1[2 * j] + t1 * w1[2 * j + 1] + b1[j], 0.f);
#pragma unroll
        for (int o = 0; o < 8; o++) acc[o] += hv * w2[o * 512 + j];
    }
#pragma unroll
    for (int o = 0; o < 8; o++) acc[o] = warp_sum(acc[o]);
    __shared__ float sh[4][8];
    int wp = tid >> 5, lane = tid & 31;
    if (lane == 0)
#pragma unroll
        for (int o = 0; o < 8; o++) sh[wp][o] = acc[o];
    __syncthreads();
    if (tid < 8)
        g_cpb[(size_t)row * 8 + tid] =
            sh[0][tid] + sh[1][tid] + sh[2][tid] + sh[3][tid] + b2[tid];
}

// ================ K1: pool logits via mma (S = Qs @ Kp^T, 3-term) ============
__global__ void __launch_bounds__(256)
pool_logits() {
    __shared__ __align__(16) uint16_t sQh[128 * 40];
    __shared__ __align__(16) uint16_t sQl[128 * 40];
    __shared__ __align__(16) uint16_t sKh[64 * 40];
    __shared__ __align__(16) uint16_t sKl[64 * 40];
    const int mtile = blockIdx.x, bh = blockIdx.y;
    const int b = bh >> 3, h = bh & 7;
    const int tid = threadIdx.x, lane = tid & 31, wid = tid >> 5;
    const int wm = wid * 16;
    const int n0 = mtile * 128;
    for (int i = tid; i < 512; i += 256) {
        int row = i >> 2, part = i & 3;
        size_t src = ((size_t)(b * NTOK + n0 + row)) * CDIM + h * HD + part * 8;
        cp16(smem_u32(sQh + row * 40 + part * 8), g_qsh + src);
        cp16(smem_u32(sQl + row * 40 + part * 8), g_qsl + src);
    }
    {
        int i = tid;
        if (i < 256) {
            int row = i >> 2, part = i & 3;
            size_t src = ((size_t)(b * PLP + row)) * CDIM + h * HD + part * 8;
            cp16(smem_u32(sKh + row * 40 + part * 8), g_kph + src);
            cp16(smem_u32(sKl + row * 40 + part * 8), g_kpl + src);
        }
    }
    CP_COMMIT(); CP_WAIT0();
    __syncthreads();
    float acc[8][4] = {};
#pragma unroll
    for (int ks = 0; ks < 2; ks++) {
        uint32_t qh[4], ql[4];
        const int arow = lane & 15, acol = ks * 16 + (lane >> 4) * 8;
        ldsm_x4(qh, smem_u32(sQh + (wm + arow) * 40 + acol));
        ldsm_x4(ql, smem_u32(sQl + (wm + arow) * 40 + acol));
        const int brow0 = lane & 7;
        const int bcol = ks * 16 + ((lane >> 3) & 1) * 8;
#pragma unroll
        for (int j = 0; j < 8; j++) {
            uint32_t kh[2], kl[2];
            ldsm_x2(kh, smem_u32(sKh + (brow0 + j * 8) * 40 + bcol));
            ldsm_x2(kl, smem_u32(sKl + (brow0 + j * 8) * 40 + bcol));
            mma_f16(acc[j], qh, kh);
            mma_f16(acc[j], ql, kh);
            mma_f16(acc[j], qh, kl);
        }
    }
    int r0 = n0 + wm + (lane >> 2);
#pragma unroll
    for (int j = 0; j < 8; j++) {
        int col = j * 8 + (lane & 3) * 2;
        float2 a; a.x = acc[j][0]; a.y = acc[j][1];
        float2 c; c.x = acc[j][2]; c.y = acc[j][3];
        *(float2*)(g_spool + ((size_t)bh * NTOK + r0) * PLP + col) = a;
        *(float2*)(g_spool + ((size_t)bh * NTOK + r0 + 8) * PLP + col) = c;
    }
}

// ================ K2: local logits + softmax + local AV ======================
#define AKW 0
#define AVW 3366
#define AQS 6732
#define AQN 7788
#define ALG 8844
#define ALT 11532
#define ASMEMB ((11532 + 9 * 33 + 3) * 4)

__global__ void __launch_bounds__(1024)
attn_soft(const float* __restrict__ rpb, const float* __restrict__ lt,
          const float* __restrict__ lb, const int* __restrict__ rel_idx) {
    extern __shared__ float sh[];
    float* Kw  = sh + AKW;     // [102][33]
    float* Vw  = sh + AVW;
    float* qss = sh + AQS;     // [32][33]
    float* qns = sh + AQN;
    float* lg  = sh + ALG;     // [32][84]
    float* lts = sh + ALT;     // [9][33]
    int blk = blockIdx.x;
    int ntile = blk & 127;
    int hh = (blk >> 7) & 7;
    int b = blk >> 10;
    int bh = b * 8 + hh;
    int tid = threadIdx.x, w = tid >> 5, lane = tid & 31;
    int y = ntile >> 1, x0 = (ntile & 1) << 5;

    for (int i = tid; i < 3264; i += 1024) {
        int vec = i >> 5, d = i & 31;
        int r = vec / 34, c = vec - r * 34;
        int yy = y + r - 1, xx = x0 - 1 + c;
        float kv0 = 0.f, vv0 = 0.f;
        if ((unsigned)yy < 64u && (unsigned)xx < 64u) {
            size_t base = ((size_t)(b * NTOK + yy * 64 + xx)) * 512 + hh * 32 + d;
            kv0 = g_kv[base];
            vv0 = g_kv[base + 256];
        }
        Kw[vec * 33 + d] = kv0;
        Vw[vec * 33 + d] = vv0;
    }
    if (tid < 288) {
        int d = tid / 9, l = tid - d * 9;
        lts[l * 33 + d] = lt[hh * 288 + tid];
    }
    int n = ntile * 32 + w;
    size_t qoff = ((size_t)(b * NTOK + n)) * 256 + hh * 32 + lane;
    qss[w * 33 + lane] = __half2float(g_qsh[qoff]) + __half2float(g_qsl[qoff]);
    qns[w * 33 + lane] = g_q[qoff];
    __syncthreads();

    int xl = n & 31;
    const int* rix = rel_idx + (size_t)n * 64;
    {
        int o = lane;
        if (o < 18) {
            const float* kr;
            const float* qr;
            float bias;
            int slot;
            if (o < 9) {
                int r = o / 3, dc = o - r * 3;
                kr = Kw + (r * 34 + xl + dc) * 33;
                qr = qss + w * 33;
                bias = rpb[hh * 9 + o];
                slot = 64 + o;
            } else {
                int l = o - 9;
                kr = lts + l * 33;
                qr = qns + w * 33;
                bias = lb[hh * 9 + l];
                slot = 73 + l;
            }
            float acc = bias;
#pragma unroll
            for (int d = 0; d < 32; d++) acc += qr[d] * kr[d];
            lg[w * 84 + slot] = acc;
        }
    }
    __syncwarp();
    size_t soff = ((size_t)bh * NTOK + n) * 64;
    float s0 = g_spool[soff + lane] + g_cpb[(size_t)rix[lane] * 8 + hh];
    float s1 = g_spool[soff + 32 + lane] + g_cpb[(size_t)rix[lane + 32] * 8 + hh];
    float l0 = (lane < 9) ? lg[w * 84 + 64 + lane] : -3.4e38f;
    float mx = warp_max(fmaxf(fmaxf(s0, s1), l0));
    float e0 = expf(s0 - mx), e1 = expf(s1 - mx);
    float e2 = (lane < 9) ? expf(l0 - mx) : 0.f;
    float inv = 1.0f / warp_sum(e0 + e1 + e2);
    float p0 = e0 * inv, p1 = e1 * inv;
    __half p0h = __float2half_rn(p0);
    __half p1h = __float2half_rn(p1);
    g_ph2[soff + lane] = p0h;
    g_pl2[soff + lane] = __float2half_rn(p0 - __half2float(p0h));
    g_ph2[soff + 32 + lane] = p1h;
    g_pl2[soff + 32 + lane] = __float2half_rn(p1 - __half2float(p1h));
    if (lane < 9) lg[w * 84 + lane] = e2 * inv + lg[w * 84 + 73 + lane];
    __syncwarp();
    float outv = 0.f;
#pragma unroll
    for (int l = 0; l < 9; l++) {
        int r = l / 3, dc = l - r * 3;
        outv += lg[w * 84 + l] * Vw[(r * 34 + xl + dc) * 33 + lane];
    }
    g_lout[(size_t)bh * (NTOK * HD) + (size_t)n * HD + lane] = outv;
}

// ================ K3: pool AV via mma (X = P @ Vp), add local, gate ==========
__global__ void __launch_bounds__(256)
pool_av() {
    __shared__ __align__(16) uint16_t sPh[128 * 72];
    __shared__ __align__(16) uint16_t sPl[128 * 72];
    __shared__ __align__(16) uint16_t sVt[32 * 72];
    const int mtile = blockIdx.x, bh = blockIdx.y;
    const int b = bh >> 3, h = bh & 7;
    const int tid = threadIdx.x, lane = tid & 31, wid = tid >> 5;
    const int wm = wid * 16;
    const int n0 = mtile * 128;
    for (int i = tid; i < 1024; i += 256) {
        int row = i >> 3, part = i & 7;
        size_t src = ((size_t)bh * NTOK + n0 + row) * 64 + part * 8;
        cp16(smem_u32(sPh + row * 72 + part * 8), g_ph2 + src);
        cp16(smem_u32(sPl + row * 72 + part * 8), g_pl2 + src);
    }
    CP_COMMIT();
    for (int i = tid; i < 2048; i += 256) {
        int p = i >> 5, d = i & 31;
        sVt[d * 72 + p] =
            *(const uint16_t*)&g_vph[((size_t)(b * PLP + p)) * CDIM + h * HD + d];
    }
    CP_WAIT0();
    __syncthreads();
    float acc[4][4] = {};
#pragma unroll
    for (int kc = 0; kc < 4; kc++) {
        uint32_t ph[4], pl[4];
        const int arow = lane & 15, acol = kc * 16 + (lane >> 4) * 8;
        ldsm_x4(ph, smem_u32(sPh + (wm + arow) * 72 + acol));
        ldsm_x4(pl, smem_u32(sPl + (wm + arow) * 72 + acol));
        const int brow0 = lane & 7;
        const int bcol = kc * 16 + ((lane >> 3) & 1) * 8;
#pragma unroll
        for (int j = 0; j < 4; j++) {
            uint32_t bv[2];
            ldsm_x2(bv, smem_u32(sVt + (brow0 + j * 8) * 72 + bcol));
            mma_f16(acc[j], ph, bv);
            mma_f16(acc[j], pl, bv);
        }
    }
    int r0 = n0 + wm + (lane >> 2);
#pragma unroll
    for (int j = 0; j < 4; j++) {
        int d = j * 8 + (lane & 3) * 2;
#pragma unroll
        for (int hf = 0; hf < 2; hf++) {
            int n = r0 + hf * 8;
            float2 lo = *(const float2*)(g_lout + (size_t)bh * (NTOK * HD) +
                                         (size_t)n * HD + d);
            float gt = g_gate[((size_t)(b * NTOK + n)) * 8 + h];
            float o0 = (acc[j][hf * 2 + 0] + lo.x) * gt;
            float o1 = (acc[j][hf * 2 + 1] + lo.y) * gt;
            *(__half2*)(g_ah + ((size_t)(b * NTOK + n)) * CDIM + h * HD + d) =
                __floats2half2_rn(o0, o1);
        }
    }
}

// ---------------- launch ----------------------------------------------------
extern "C" void kernel_launch(void* const* d_in, const int* in_sizes, int n_in,
                              void* d_out, int out_size) {
    const float* x      = (const float*)d_in[0];
    const float* rct    = (const float*)d_in[1];
    const float* q_w    = (const float*)d_in[2];
    const float* q_b    = (const float*)d_in[3];
    const float* kv_w   = (const float*)d_in[4];
    const float* kv_b   = (const float*)d_in[5];
    const float* temp   = (const float*)d_in[6];
    const float* qe     = (const float*)d_in[7];
    const float* rpb    = (const float*)d_in[8];
    const float* lt     = (const float*)d_in[9];
    const float* lb     = (const float*)d_in[10];
    const float* cpb1_w = (const float*)d_in[11];
    const float* cpb1_b = (const float*)d_in[12];
    const float* cpb2_w = (const float*)d_in[13];
    const float* cpb2_b = (const float*)d_in[14];
    const float* sr_w   = (const float*)d_in[15];
    const float* sr_b   = (const float*)d_in[16];
    const float* norm_g = (const float*)d_in[17];
    const float* norm_b = (const float*)d_in[18];
    const float* wg_w   = (const float*)d_in[19];
    const float* wg0_w  = (const float*)d_in[20];
    const float* wg1_w  = (const float*)d_in[21];
    const float* proj_w = (const float*)d_in[22];
    const float* proj_b = (const float*)d_in[23];
    const int*   ridx   = (const int*)d_in[24];
    float* out = (float*)d_out;

    float *pq, *pkv, *psr, *pkvp;
    __half *pxh, *pwh, *pwl, *pph, *pah;
    cudaGetSymbolAddress((void**)&pq,   g_q);
    cudaGetSymbolAddress((void**)&pkv,  g_kv);
    cudaGetSymbolAddress((void**)&psr,  g_sr);
    cudaGetSymbolAddress((void**)&pkvp, g_kvp);
    cudaGetSymbolAddress((void**)&pxh,  g_xh);
    cudaGetSymbolAddress((void**)&pwh,  g_wh);
    cudaGetSymbolAddress((void**)&pwl,  g_wl);
    cudaGetSymbolAddress((void**)&pph,  g_ph);
    cudaGetSymbolAddress((void**)&pah,  g_ah);

    cudaFuncSetAttribute(gemm_f16<0>,
                         cudaFuncAttributeMaxDynamicSharedMemorySize, GSMEM);
    cudaFuncSetAttribute(gemm_f16<1>,
                         cudaFuncAttributeMaxDynamicSharedMemorySize, GSMEM);
    cudaFuncSetAttribute(attn_soft,
                         cudaFuncAttributeMaxDynamicSharedMemorySize, ASMEMB);

    const int M = BATCH * NTOK;                       // 16384

    conv_x_gate<<<M / 8, 256>>>(x, wg_w, wg0_w, wg1_w);             // 0
    conv_w<<<320, 256>>>(q_w, kv_w, sr_w, proj_w);                  // 1
    cpb_kernel<<<TBLN, 128>>>(rct, cpb1_w, cpb1_b, cpb2_w, cpb2_b); // 2
    dim3 gf(8, M / 128);
    gemm_f16<0><<<gf, 256, GSMEM>>>(pxh, pwh, pwl,                  // 3 (profiled)
                                    pq, pkv, psr, q_b, kv_b, sr_b, 0,
                                    temp, qe);
    pool_ln<<<BATCH * PLP, 256>>>(norm_g, norm_b);                  // 4
    dim3 gp(4, 2);
    gemm_f16<1><<<gp, 256, GSMEM>>>(pph, pwh + 256 * 256, pwl + 256 * 256,
                                    pkvp, nullptr, nullptr, kv_b, nullptr,
                                    nullptr, 512, nullptr, nullptr); // 5
    kvpool_post<<<BATCH * PLP, 256>>>();                            // 6
    dim3 ga(NTOK / 128, BH);
    pool_logits<<<ga, 256>>>();                                     // 7
    attn_soft<<<BATCH * NH * (NTOK / 32), 1024, ASMEMB>>>(rpb, lt, lb, ridx); // 8
    pool_av<<<ga, 256>>>();                                         // 9
    dim3 gj(2, M / 128);
    gemm_f16<1><<<gj, 256, GSMEM>>>(pah, pwh + 1024 * 256, pwl + 1024 * 256,
                                    out, nullptr, nullptr, proj_b, nullptr,
                                    nullptr, 256, nullptr, nullptr); // 10
}